// round 5
// baseline (speedup 1.0000x reference)
#include <cuda_runtime.h>
#include <cstdint>

// Problem constants
#define BB 2
#define SS 2048
#define DM 2048
#define NH 32
#define NKV 8
#define HD 64

// ---------------------------------------------------------------------------
// Scratch (allocation-free rule: __device__ globals)
// ---------------------------------------------------------------------------
__device__ __align__(1024) float g_q[(size_t)BB * SS * NH * HD];
__device__ __align__(1024) float g_k[(size_t)BB * SS * NKV * HD];
__device__ __align__(1024) float g_v[(size_t)BB * SS * NKV * HD];
__device__ __align__(1024) float g_att[(size_t)BB * SS * NH * HD];

// ---------------------------------------------------------------------------
// Helpers
// ---------------------------------------------------------------------------
__device__ __forceinline__ uint32_t smem_u32(const void* p) {
    uint32_t a;
    asm("{ .reg .u64 t; cvta.to.shared.u64 t, %1; cvt.u32.u64 %0, t; }" : "=r"(a) : "l"(p));
    return a;
}
__device__ __forceinline__ float rna_tf32(float v) {
    uint32_t r;
    asm("cvt.rna.tf32.f32 %0, %1;" : "=r"(r) : "f"(v));
    return __uint_as_float(r);
}
__device__ __forceinline__ uint32_t rna_tf32_u(float v) {
    uint32_t r;
    asm("cvt.rna.tf32.f32 %0, %1;" : "=r"(r) : "f"(v));
    return r;
}
__device__ __forceinline__ void cp_async16(uint32_t smem, const void* gmem) {
    asm volatile("cp.async.cg.shared.global [%0], [%1], 16;" :: "r"(smem), "l"(gmem));
}
#define CP_COMMIT() asm volatile("cp.async.commit_group;" ::: "memory")
#define CP_WAIT(n)  asm volatile("cp.async.wait_group %0;" :: "n"(n) : "memory")

// m16n8k8 tf32 MMA (sm_80+ baseline; runs on Blackwell legacy HMMA pipe)
__device__ __forceinline__ void mma16n8k8(float* d, const uint32_t* a, const uint32_t* b) {
    asm volatile(
        "mma.sync.aligned.m16n8k8.row.col.f32.tf32.tf32.f32 "
        "{%0,%1,%2,%3}, {%4,%5,%6,%7}, {%8,%9}, {%0,%1,%2,%3};"
        : "+f"(d[0]), "+f"(d[1]), "+f"(d[2]), "+f"(d[3])
        : "r"(a[0]), "r"(a[1]), "r"(a[2]), "r"(a[3]), "r"(b[0]), "r"(b[1]));
}

// ---------------------------------------------------------------------------
// tf32 mma.sync GEMM: C[M,N] = A[M,K] @ B[K,N], both row-major fp32.
// tf32 RNA rounding applied IN-REGISTER to both operands (no pre-pass).
// BM=BN=128, BK=32, 256 threads / 8 warps (warp tile 32x64), 3-stage cp.async.
// Epilogue modes: 0 = plain fp32 store, 1 = rope(scale)+rna, 2 = rope+rna,
//                 3 = rna only.
// ---------------------------------------------------------------------------
#define GASZ 4608            // A floats per stage (128*36)
#define GBSZ 4352            // B floats per stage (32*136)
#define GSTG (GASZ + GBSZ)   // 8960 floats
#define GEMM_SMEM (3 * GSTG * 4)

__global__ __launch_bounds__(256) void gemm_tf32_kernel(
    const float* __restrict__ A, const float* __restrict__ Bw,
    float* __restrict__ C, int M, int N, int K,
    int mode, float scale,
    const float* __restrict__ fcos, const float* __restrict__ fsin)
{
    extern __shared__ float sm[];
    const int tid = threadIdx.x;
    const int wid = tid >> 5, lid = tid & 31;
    const int wm = wid & 3, wn = wid >> 2;       // 4x2 warp grid
    const int lr = lid >> 2, lc = lid & 3;
    const int bm = blockIdx.y * 128, bn = blockIdx.x * 128;

    const float* Ag = A + (size_t)bm * K;
    const uint32_t sb = smem_u32(sm);

    float acc[2][8][4];
#pragma unroll
    for (int mt = 0; mt < 2; mt++)
#pragma unroll
        for (int nt = 0; nt < 8; nt++)
#pragma unroll
            for (int i = 0; i < 4; i++) acc[mt][nt][i] = 0.f;

    auto load_stage = [&](int s) {
        const int st = s - (s / 3) * 3;
        const float* Ab = Ag + s * 32;
        const float* Bb = Bw + (size_t)(s * 32) * N + bn;
#pragma unroll
        for (int i = 0; i < 4; i++) {
            int c = tid + i * 256;
            int ar = c >> 3, ac = (c & 7) * 4;
            cp_async16(sb + (uint32_t)(st * GSTG + ar * 36 + ac) * 4,
                       Ab + (size_t)ar * K + ac);
            int br = c >> 5, bc = (c & 31) * 4;
            cp_async16(sb + (uint32_t)(st * GSTG + GASZ + br * 136 + bc) * 4,
                       Bb + (size_t)br * N + bc);
        }
    };

    const int nk = K / 32;
#pragma unroll
    for (int s = 0; s < 3; s++) { if (s < nk) load_stage(s); CP_COMMIT(); }

    for (int s = 0; s < nk; s++) {
        CP_WAIT(2);
        __syncthreads();
        const int st = s - (s / 3) * 3;
        const float* As = sm + st * GSTG + (wm * 32 + lr) * 36 + lc;
#pragma unroll
        for (int kk = 0; kk < 4; kk++) {
            uint32_t af[2][4], bf[8][2];
#pragma unroll
            for (int mt = 0; mt < 2; mt++) {
                const float* p = As + mt * 16 * 36 + kk * 8;
                af[mt][0] = rna_tf32_u(p[0]);
                af[mt][1] = rna_tf32_u(p[8 * 36]);
                af[mt][2] = rna_tf32_u(p[4]);
                af[mt][3] = rna_tf32_u(p[8 * 36 + 4]);
            }
            const float* Bk = sm + st * GSTG + GASZ + (kk * 8 + lc) * 136 + wn * 64 + lr;
#pragma unroll
            for (int nt = 0; nt < 8; nt++) {
                bf[nt][0] = rna_tf32_u(Bk[nt * 8]);
                bf[nt][1] = rna_tf32_u(Bk[4 * 136 + nt * 8]);
            }
#pragma unroll
            for (int mt = 0; mt < 2; mt++)
#pragma unroll
                for (int nt = 0; nt < 8; nt++)
                    mma16n8k8(acc[mt][nt], af[mt], bf[nt]);
        }
        __syncthreads();
        if (s + 3 < nk) load_stage(s + 3);
        CP_COMMIT();
    }

    // epilogue
#pragma unroll
    for (int mt = 0; mt < 2; mt++) {
        const int r0 = bm + wm * 32 + mt * 16 + lr;   // rows r0, r0+8
        const int s0 = r0 & (SS - 1);
        const int s1 = (r0 + 8) & (SS - 1);
#pragma unroll
        for (int nt = 0; nt < 8; nt++) {
            const int col = bn + wn * 64 + nt * 8 + lc * 2;
            float a0 = acc[mt][nt][0], a1 = acc[mt][nt][1];
            float a2 = acc[mt][nt][2], a3 = acc[mt][nt][3];
            float2 v0, v1;
            if (mode == 0) {
                v0 = make_float2(a0, a1);
                v1 = make_float2(a2, a3);
            } else if (mode == 3) {
                v0 = make_float2(rna_tf32(a0), rna_tf32(a1));
                v1 = make_float2(rna_tf32(a2), rna_tf32(a3));
            } else {  // rope modes
                const int pidx = (col & 63) >> 1;
                const float c0 = fcos[s0 * 32 + pidx], si0 = fsin[s0 * 32 + pidx];
                const float c1 = fcos[s1 * 32 + pidx], si1 = fsin[s1 * 32 + pidx];
                v0 = make_float2(rna_tf32(scale * (a0 * c0 - a1 * si0)),
                                 rna_tf32(scale * (a0 * si0 + a1 * c0)));
                v1 = make_float2(rna_tf32(scale * (a2 * c1 - a3 * si1)),
                                 rna_tf32(scale * (a2 * si1 + a3 * c1)));
            }
            *(float2*)&C[(size_t)r0 * N + col] = v0;
            *(float2*)&C[(size_t)(r0 + 8) * N + col] = v1;
        }
    }
}

// ---------------------------------------------------------------------------
// Flash attention (causal, GQA) via mma.sync tf32.
// Block = 128 q-rows x head x batch; 8 warps (256 thr), warp owns 16 rows.
// K rows stored PERMUTED (slot psi(j): j<4 -> 2j else 2j-7) so the S
// accumulator layout coincides with the PV A-fragment layout: no shuffles.
// 2-stage cp.async double buffer for 64-key K/V tiles.
// Heavy q-tiles scheduled first (reversed tile order) for wave balance.
// ---------------------------------------------------------------------------
#define KS_F (64 * 68)
#define VS_F (64 * 72)
#define AST_F (KS_F + VS_F)
#define ATTN_SMEM (2 * AST_F * 4)

__global__ __launch_bounds__(256, 2) void attn_kernel(
    const float* __restrict__ Q, const float* __restrict__ Kg,
    const float* __restrict__ Vg, float* __restrict__ O)
{
    extern __shared__ float sm[];
    const uint32_t sb = smem_u32(sm);

    const int tile = gridDim.x - 1 - blockIdx.x;   // heavy tiles first
    const int m0 = tile * 128;
    const int h = blockIdx.y;
    const int b = blockIdx.z;
    const int kvh = h >> 2;
    const int tid = threadIdx.x;
    const int w = tid >> 5, lid = tid & 31;
    const int lr = lid >> 2, lc = lid & 3;
    const int row0 = m0 + w * 16 + lr;   // second row-half is row0+8

    const size_t kvs = NKV * HD;  // 512
    const float* Kbase = Kg + (size_t)b * SS * kvs + kvh * HD;
    const float* Vbase = Vg + (size_t)b * SS * kvs + kvh * HD;

    // Persistent Q fragments (scaled by 1/8, tf32-rounded in q-gemm epilogue)
    uint32_t qa[8][4];
    {
        const float* q0 = Q + ((size_t)(b * SS + row0) * NH + h) * HD;
        const float* q1 = q0 + (size_t)8 * NH * HD;
#pragma unroll
        for (int kk = 0; kk < 8; kk++) {
            qa[kk][0] = __float_as_uint(q0[kk * 8 + lc]);
            qa[kk][1] = __float_as_uint(q1[kk * 8 + lc]);
            qa[kk][2] = __float_as_uint(q0[kk * 8 + lc + 4]);
            qa[kk][3] = __float_as_uint(q1[kk * 8 + lc + 4]);
        }
    }

    float oacc[8][4];
#pragma unroll
    for (int nt = 0; nt < 8; nt++)
#pragma unroll
        for (int i = 0; i < 4; i++) oacc[nt][i] = 0.f;
    float mst0 = -1e30f, mst1 = -1e30f, lst0 = 0.f, lst1 = 0.f;

    // 1024 16B-chunks per operand, 256 threads -> 4 chunks each per operand
    auto loadKV = [&](int n0, int st) {
        const uint32_t kso = (uint32_t)(st * AST_F) * 4;
        const uint32_t vso = (uint32_t)(st * AST_F + KS_F) * 4;
#pragma unroll
        for (int i = 0; i < 4; i++) {
            int c = tid + i * 256;
            int j = c >> 4;
            int cc = (c & 15) * 4;
            int j3 = j & 7;
            int dst = (j & ~7) | ((j3 < 4) ? (2 * j3) : (2 * j3 - 7));
            cp_async16(sb + kso + (uint32_t)(dst * 68 + cc) * 4,
                       Kbase + (size_t)(n0 + j) * kvs + cc);
            cp_async16(sb + vso + (uint32_t)(j * 72 + cc) * 4,
                       Vbase + (size_t)(n0 + j) * kvs + cc);
        }
    };

    const int niter = m0 / 64 + 2;   // covers keys up to m0+127
    loadKV(0, 0);
    CP_COMMIT();

    for (int it = 0; it < niter; it++) {
        const int n0 = it * 64;
        const int st = it & 1;
        if (it + 1 < niter) {
            loadKV(n0 + 64, st ^ 1);
            CP_COMMIT();
            CP_WAIT(1);
        } else {
            CP_WAIT(0);
        }
        __syncthreads();

        const float* Ks = sm + st * AST_F;
        const float* Vs = sm + st * AST_F + KS_F;

        float s[8][4];
#pragma unroll
        for (int nt = 0; nt < 8; nt++)
#pragma unroll
            for (int i = 0; i < 4; i++) s[nt][i] = 0.f;
#pragma unroll
        for (int kk = 0; kk < 8; kk++) {
#pragma unroll
            for (int nt = 0; nt < 8; nt++) {
                uint32_t kb[2];
                const float* p = &Ks[(nt * 8 + lr) * 68 + kk * 8 + lc];
                kb[0] = __float_as_uint(p[0]);
                kb[1] = __float_as_uint(p[4]);
                mma16n8k8(s[nt], qa[kk], kb);
            }
        }

        // causal mask: needed when this key tile reaches past the warp's rows
        if (n0 + 63 > m0 + w * 16) {
#pragma unroll
            for (int nt = 0; nt < 8; nt++) {
                const int key0 = n0 + nt * 8 + lc;
                const int key1 = key0 + 4;
                if (key0 > row0) s[nt][0] = -1e30f;
                if (key1 > row0) s[nt][1] = -1e30f;
                if (key0 > row0 + 8) s[nt][2] = -1e30f;
                if (key1 > row0 + 8) s[nt][3] = -1e30f;
            }
        }

        float mx0 = -1e30f, mx1 = -1e30f;
#pragma unroll
        for (int nt = 0; nt < 8; nt++) {
            mx0 = fmaxf(mx0, fmaxf(s[nt][0], s[nt][1]));
            mx1 = fmaxf(mx1, fmaxf(s[nt][2], s[nt][3]));
        }
        mx0 = fmaxf(mx0, __shfl_xor_sync(0xffffffffu, mx0, 1));
        mx0 = fmaxf(mx0, __shfl_xor_sync(0xffffffffu, mx0, 2));
        mx1 = fmaxf(mx1, __shfl_xor_sync(0xffffffffu, mx1, 1));
        mx1 = fmaxf(mx1, __shfl_xor_sync(0xffffffffu, mx1, 2));
        const float mn0 = fmaxf(mst0, mx0), mn1 = fmaxf(mst1, mx1);
        const float corr0 = __expf(mst0 - mn0), corr1 = __expf(mst1 - mn1);
        mst0 = mn0; mst1 = mn1;
        float sum0 = 0.f, sum1 = 0.f;
#pragma unroll
        for (int nt = 0; nt < 8; nt++) {
            s[nt][0] = __expf(s[nt][0] - mn0); sum0 += s[nt][0];
            s[nt][1] = __expf(s[nt][1] - mn0); sum0 += s[nt][1];
            s[nt][2] = __expf(s[nt][2] - mn1); sum1 += s[nt][2];
            s[nt][3] = __expf(s[nt][3] - mn1); sum1 += s[nt][3];
        }
        sum0 += __shfl_xor_sync(0xffffffffu, sum0, 1);
        sum0 += __shfl_xor_sync(0xffffffffu, sum0, 2);
        sum1 += __shfl_xor_sync(0xffffffffu, sum1, 1);
        sum1 += __shfl_xor_sync(0xffffffffu, sum1, 2);
        lst0 = lst0 * corr0 + sum0;
        lst1 = lst1 * corr1 + sum1;
#pragma unroll
        for (int nt = 0; nt < 8; nt++) {
            oacc[nt][0] *= corr0; oacc[nt][1] *= corr0;
            oacc[nt][2] *= corr1; oacc[nt][3] *= corr1;
        }

        // O += P V : accumulator IS the A-fragment (permuted-K trick)
#pragma unroll
        for (int kk = 0; kk < 8; kk++) {
            uint32_t pa[4];
            pa[0] = rna_tf32_u(s[kk][0]);
            pa[1] = rna_tf32_u(s[kk][2]);
            pa[2] = rna_tf32_u(s[kk][1]);
            pa[3] = rna_tf32_u(s[kk][3]);
#pragma unroll
            for (int nt = 0; nt < 8; nt++) {
                uint32_t vb[2];
                const float* p = &Vs[(kk * 8 + lc) * 72 + nt * 8 + lr];
                vb[0] = __float_as_uint(p[0]);
                vb[1] = __float_as_uint(p[4 * 72]);
                mma16n8k8(oacc[nt], pa, vb);
            }
        }
        __syncthreads();
    }

    const float inv0 = 1.f / lst0, inv1 = 1.f / lst1;
    float* o0 = O + ((size_t)(b * SS + row0) * NH + h) * HD;
    float* o1 = o0 + (size_t)8 * NH * HD;
#pragma unroll
    for (int nt = 0; nt < 8; nt++) {
        const int col = nt * 8 + lc * 2;
        *(float2*)&o0[col] = make_float2(oacc[nt][0] * inv0, oacc[nt][1] * inv0);
        *(float2*)&o1[col] = make_float2(oacc[nt][2] * inv1, oacc[nt][3] * inv1);
    }
}

// ---------------------------------------------------------------------------
// Launch. inputs: 0=x, 1=freqs_cos, 2=freqs_sin, 3=mask(unused),
//                 4=wq, 5=wk, 6=wv, 7=wo
// ---------------------------------------------------------------------------
extern "C" void kernel_launch(void* const* d_in, const int* in_sizes, int n_in,
                              void* d_out, int out_size)
{
    const float* x = (const float*)d_in[0];
    const float* fcos = (const float*)d_in[1];
    const float* fsin = (const float*)d_in[2];
    const float* wq = (const float*)d_in[4];
    const float* wk = (const float*)d_in[5];
    const float* wv = (const float*)d_in[6];
    const float* wo = (const float*)d_in[7];
    float* out = (float*)d_out;

    float *q, *k, *v, *att;
    cudaGetSymbolAddress((void**)&q, g_q);
    cudaGetSymbolAddress((void**)&k, g_k);
    cudaGetSymbolAddress((void**)&v, g_v);
    cudaGetSymbolAddress((void**)&att, g_att);

    static bool attr_set = false;
    if (!attr_set) {
        cudaFuncSetAttribute(gemm_tf32_kernel,
                             cudaFuncAttributeMaxDynamicSharedMemorySize, GEMM_SMEM);
        cudaFuncSetAttribute(attn_kernel,
                             cudaFuncAttributeMaxDynamicSharedMemorySize, ATTN_SMEM);
        attr_set = true;
    }

    const int M = BB * SS;  // 4096

    // QKV projections with fused in-register tf32 rounding + fused RoPE/round
    gemm_tf32_kernel<<<dim3((NH * HD) / 128, M / 128), 256, GEMM_SMEM>>>(
        x, wq, q, M, NH * HD, DM, /*mode=*/1, 0.125f, fcos, fsin);
    gemm_tf32_kernel<<<dim3((NKV * HD) / 128, M / 128), 256, GEMM_SMEM>>>(
        x, wk, k, M, NKV * HD, DM, /*mode=*/2, 1.0f, fcos, fsin);
    gemm_tf32_kernel<<<dim3((NKV * HD) / 128, M / 128), 256, GEMM_SMEM>>>(
        x, wv, v, M, NKV * HD, DM, /*mode=*/3, 1.0f, fcos, fsin);

    // Attention (128-row q-tiles, permuted-K flash, cp.async double buffer)
    attn_kernel<<<dim3(SS / 128, NH, BB), 256, ATTN_SMEM>>>(q, k, v, att);

    // Output projection (plain fp32 epilogue)
    gemm_tf32_kernel<<<dim3(DM / 128, M / 128), 256, GEMM_SMEM>>>(
        att, wo, out, M, DM, DM, /*mode=*/0, 1.0f, fcos, fsin);
}

// round 6
// speedup vs baseline: 1.7555x; 1.7555x over previous
#include <cuda_runtime.h>
#include <cuda_fp16.h>
#include <cstdint>

// Problem constants
#define BB 2
#define SS 2048
#define DM 2048
#define NH 32
#define NKV 8
#define HD 64

#define LOG2E 1.4426950408889634f

// ---------------------------------------------------------------------------
// Scratch (allocation-free rule: __device__ globals)
// ---------------------------------------------------------------------------
__device__ __align__(1024) __half g_xh[(size_t)BB * SS * DM];
__device__ __align__(1024) __half g_wqT[(size_t)(NH * HD) * DM];
__device__ __align__(1024) __half g_wkT[(size_t)(NKV * HD) * DM];
__device__ __align__(1024) __half g_wvT[(size_t)(NKV * HD) * DM];
__device__ __align__(1024) __half g_woT[(size_t)DM * DM];
__device__ __align__(1024) __half g_q[(size_t)BB * SS * NH * HD];
__device__ __align__(1024) __half g_k[(size_t)BB * SS * NKV * HD];
__device__ __align__(1024) __half g_v[(size_t)BB * SS * NKV * HD];
__device__ __align__(1024) __half g_att[(size_t)BB * SS * NH * HD];
__device__ __align__(1024) uint32_t g_vp[(size_t)BB * NKV * (SS / 2) * HD];

// ---------------------------------------------------------------------------
// Helpers
// ---------------------------------------------------------------------------
__device__ __forceinline__ uint32_t smem_u32(const void* p) {
    uint32_t a;
    asm("{ .reg .u64 t; cvta.to.shared.u64 t, %1; cvt.u32.u64 %0, t; }" : "=r"(a) : "l"(p));
    return a;
}
// pack two fp32 -> f16x2 (lo, hi) with round-to-nearest-even
__device__ __forceinline__ uint32_t h2pack(float lo, float hi) {
    uint32_t d;
    asm("cvt.rn.f16x2.f32 %0, %1, %2;" : "=r"(d) : "f"(hi), "f"(lo));
    return d;
}
__device__ __forceinline__ void cp_async16(uint32_t smem, const void* gmem) {
    asm volatile("cp.async.cg.shared.global [%0], [%1], 16;" :: "r"(smem), "l"(gmem));
}
#define CP_COMMIT() asm volatile("cp.async.commit_group;" ::: "memory")
#define CP_WAIT(n)  asm volatile("cp.async.wait_group %0;" :: "n"(n) : "memory")

// m16n8k16 fp16 MMA, fp32 accumulate (sm_80+ baseline; legacy HMMA pipe)
__device__ __forceinline__ void mma16n8k16(float* d, const uint32_t* a, const uint32_t* b) {
    asm volatile(
        "mma.sync.aligned.m16n8k16.row.col.f32.f16.f16.f32 "
        "{%0,%1,%2,%3}, {%4,%5,%6,%7}, {%8,%9}, {%0,%1,%2,%3};"
        : "+f"(d[0]), "+f"(d[1]), "+f"(d[2]), "+f"(d[3])
        : "r"(a[0]), "r"(a[1]), "r"(a[2]), "r"(a[3]), "r"(b[0]), "r"(b[1]));
}

// ---------------------------------------------------------------------------
// fp16 mma.sync GEMM: C[M,N] = A[M,K] @ Bt[N,K]^T  (fp16 operands, K-major)
// BM=BN=128, BK=32, 256 threads / 8 warps (warp tile 32x64), 3-stage cp.async.
// smem rows padded to 40 halves (20 words): all fragment LDS conflict-free.
// Epilogue modes: 0 = fp32 store, 1 = rope(scale)->fp16, 2 = rope->fp16,
//                 3 = fp16 store.
// ---------------------------------------------------------------------------
#define GLD 40                 // halves per smem row
#define GAH (128 * GLD)        // halves per operand tile (5120)
#define GSTH (2 * GAH)         // halves per stage (10240)
#define GEMM_SMEM (3 * GSTH * 2)

__global__ __launch_bounds__(256) void gemm_f16_kernel(
    const __half* __restrict__ A, const __half* __restrict__ Bt,
    void* __restrict__ Cv, int M, int N, int K,
    int mode, float scale,
    const float* __restrict__ fcos, const float* __restrict__ fsin)
{
    extern __shared__ __half smh[];
    const int tid = threadIdx.x;
    const int wid = tid >> 5, lid = tid & 31;
    const int wm = wid & 3, wn = wid >> 2;       // 4x2 warp grid
    const int lr = lid >> 2, lc = lid & 3;
    const int bm = blockIdx.y * 128, bn = blockIdx.x * 128;

    const uint32_t sb = smem_u32(smh);

    float acc[2][8][4];
#pragma unroll
    for (int mt = 0; mt < 2; mt++)
#pragma unroll
        for (int nt = 0; nt < 8; nt++)
#pragma unroll
            for (int i = 0; i < 4; i++) acc[mt][nt][i] = 0.f;

    auto load_stage = [&](int s) {
        const int st = s - (s / 3) * 3;
        const __half* Ab = A + (size_t)bm * K + s * 32;
        const __half* Bb = Bt + (size_t)bn * K + s * 32;
#pragma unroll
        for (int i = 0; i < 2; i++) {
            int c = tid + i * 256;
            int row = c >> 2, cc = c & 3;        // 4 x 16B chunks per 32-half row
            cp_async16(sb + (uint32_t)(st * GSTH + row * GLD + cc * 8) * 2,
                       Ab + (size_t)row * K + cc * 8);
            cp_async16(sb + (uint32_t)(st * GSTH + GAH + row * GLD + cc * 8) * 2,
                       Bb + (size_t)row * K + cc * 8);
        }
    };

    const int nk = K / 32;
#pragma unroll
    for (int s = 0; s < 3; s++) { if (s < nk) load_stage(s); CP_COMMIT(); }

    for (int s = 0; s < nk; s++) {
        CP_WAIT(2);
        __syncthreads();
        const int st = s - (s / 3) * 3;
        const __half* As = smh + st * GSTH + (wm * 32 + lr) * GLD + 2 * lc;
        const __half* Bs = smh + st * GSTH + GAH + (wn * 64 + lr) * GLD + 2 * lc;
#pragma unroll
        for (int kk = 0; kk < 2; kk++) {         // two k16 steps cover BK=32
            uint32_t af[2][4], bf[8][2];
#pragma unroll
            for (int mt = 0; mt < 2; mt++) {
                const __half* p = As + mt * 16 * GLD + kk * 16;
                af[mt][0] = *(const uint32_t*)(p);
                af[mt][1] = *(const uint32_t*)(p + 8 * GLD);
                af[mt][2] = *(const uint32_t*)(p + 8);
                af[mt][3] = *(const uint32_t*)(p + 8 * GLD + 8);
            }
#pragma unroll
            for (int nt = 0; nt < 8; nt++) {
                const __half* p = Bs + nt * 8 * GLD + kk * 16;
                bf[nt][0] = *(const uint32_t*)(p);
                bf[nt][1] = *(const uint32_t*)(p + 8);
            }
#pragma unroll
            for (int mt = 0; mt < 2; mt++)
#pragma unroll
                for (int nt = 0; nt < 8; nt++)
                    mma16n8k16(acc[mt][nt], af[mt], bf[nt]);
        }
        __syncthreads();
        if (s + 3 < nk) load_stage(s + 3);
        CP_COMMIT();
    }

    // epilogue
#pragma unroll
    for (int mt = 0; mt < 2; mt++) {
        const int r0 = bm + wm * 32 + mt * 16 + lr;
        const int s0 = r0 & (SS - 1);
        const int s1 = (r0 + 8) & (SS - 1);
#pragma unroll
        for (int nt = 0; nt < 8; nt++) {
            const int col = bn + wn * 64 + nt * 8 + lc * 2;
            float a0 = acc[mt][nt][0], a1 = acc[mt][nt][1];
            float a2 = acc[mt][nt][2], a3 = acc[mt][nt][3];
            if (mode == 0) {
                float* C = (float*)Cv;
                *(float2*)&C[(size_t)r0 * N + col] = make_float2(a0, a1);
                *(float2*)&C[(size_t)(r0 + 8) * N + col] = make_float2(a2, a3);
            } else if (mode == 3) {
                __half* C = (__half*)Cv;
                *(uint32_t*)&C[(size_t)r0 * N + col] = h2pack(a0, a1);
                *(uint32_t*)&C[(size_t)(r0 + 8) * N + col] = h2pack(a2, a3);
            } else {  // rope modes (pairs a0/a1 and a2/a3 are the even/odd lanes)
                const int pidx = (col & 63) >> 1;
                const float c0 = fcos[s0 * 32 + pidx], si0 = fsin[s0 * 32 + pidx];
                const float c1 = fcos[s1 * 32 + pidx], si1 = fsin[s1 * 32 + pidx];
                __half* C = (__half*)Cv;
                *(uint32_t*)&C[(size_t)r0 * N + col] =
                    h2pack(scale * (a0 * c0 - a1 * si0), scale * (a0 * si0 + a1 * c0));
                *(uint32_t*)&C[(size_t)(r0 + 8) * N + col] =
                    h2pack(scale * (a2 * c1 - a3 * si1), scale * (a2 * si1 + a3 * c1));
            }
        }
    }
}

// ---------------------------------------------------------------------------
// fp32 -> fp16 elementwise
// ---------------------------------------------------------------------------
__global__ void cvt_h_kernel(const float4* __restrict__ in,
                             uint2* __restrict__ out, int n4)
{
    int i = blockIdx.x * 256 + threadIdx.x;
    if (i >= n4) return;
    float4 v = in[i];
    uint2 o;
    o.x = h2pack(v.x, v.y);
    o.y = h2pack(v.z, v.w);
    out[i] = o;
}

// ---------------------------------------------------------------------------
// Transpose + fp16 convert: out[C,R] fp16 = in[R,C]^T
// ---------------------------------------------------------------------------
__global__ void transpose_h_kernel(const float* __restrict__ in,
                                   __half* __restrict__ out, int R, int C)
{
    __shared__ float t[32][33];
    const int bx = blockIdx.x * 32;
    const int by = blockIdx.y * 32;
    const int x = bx + threadIdx.x;
#pragma unroll
    for (int i = threadIdx.y; i < 32; i += 8)
        t[i][threadIdx.x] = in[(size_t)(by + i) * C + x];
    __syncthreads();
    const int xo = by + threadIdx.x;
#pragma unroll
    for (int i = threadIdx.y; i < 32; i += 8)
        out[(size_t)(bx + i) * R + xo] = __float2half(t[threadIdx.x][i]);
}

// ---------------------------------------------------------------------------
// Pack V into key-pair-major b32: vp[((b*NKV+kvh)*1024+sp)*64+d] =
//   { lo = V[2sp][d], hi = V[2sp+1][d] }
// ---------------------------------------------------------------------------
__global__ void packv_kernel(const __half* __restrict__ V,
                             uint32_t* __restrict__ vp)
{
    int i = blockIdx.x * 256 + threadIdx.x;   // total = BB*NKV*1024*64 = 1M
    const int d = i & 63;
    const int sp = (i >> 6) & 1023;
    const int kvh = (i >> 16) & 7;
    const int b = i >> 19;
    const size_t base = ((size_t)(b * SS + 2 * sp)) * (NKV * HD) + kvh * 64 + d;
    const uint16_t lo = __half_as_ushort(V[base]);
    const uint16_t hi = __half_as_ushort(V[base + NKV * HD]);
    vp[i] = (uint32_t)lo | ((uint32_t)hi << 16);
}

// ---------------------------------------------------------------------------
// Flash attention (causal, GQA) via mma.sync fp16 (f32 accumulate).
// Block = 128 q-rows x head x batch; 8 warps, warp owns 16 rows.
// fp16 A-fragments pack adjacent column pairs == S accumulator layout, so the
// PV operand is built by packing (c0,c1)/(c2,c3) -> f16x2: no permutation,
// no shuffles. V is pre-packed key-pair-major so PV B-frags are single LDS32s.
// 2-stage cp.async double buffer. exp2 domain (log2e folded into q scale).
// ---------------------------------------------------------------------------
#define AKLD 72      // halves per K row (64 + pad)  -> 36 words
#define AVLD 72      // words per Vp row (64 + pad)
#define KS_H (64 * AKLD)
#define VP_W (32 * AVLD)

__global__ __launch_bounds__(256, 2) void attn_kernel(
    const __half* __restrict__ Q, const __half* __restrict__ Kg,
    const uint32_t* __restrict__ Vp, __half* __restrict__ O)
{
    __shared__ __align__(16) __half Ksm[2][KS_H];
    __shared__ __align__(16) uint32_t Vsm[2][VP_W];

    const int tile = gridDim.x - 1 - blockIdx.x;   // heavy tiles first
    const int m0 = tile * 128;
    const int h = blockIdx.y;
    const int b = blockIdx.z;
    const int kvh = h >> 2;
    const int tid = threadIdx.x;
    const int w = tid >> 5, lid = tid & 31;
    const int lr = lid >> 2, lc = lid & 3;
    const int row0 = m0 + w * 16 + lr;   // second row-half is row0+8

    const int kvs = NKV * HD;  // 512
    const __half* Kbase = Kg + (size_t)b * SS * kvs + kvh * 64;
    const uint32_t* Vpb = Vp + ((size_t)(b * NKV + kvh) * (SS / 2)) * 64;

    // Persistent Q fragments (q has 0.125*log2e folded in, fp16)
    uint32_t qa[4][4];
    {
        const __half* q0 = Q + ((size_t)(b * SS + row0) * NH + h) * HD;
        const __half* q1 = q0 + (size_t)8 * NH * HD;
#pragma unroll
        for (int kk = 0; kk < 4; kk++) {
            qa[kk][0] = *(const uint32_t*)(q0 + kk * 16 + 2 * lc);
            qa[kk][1] = *(const uint32_t*)(q1 + kk * 16 + 2 * lc);
            qa[kk][2] = *(const uint32_t*)(q0 + kk * 16 + 2 * lc + 8);
            qa[kk][3] = *(const uint32_t*)(q1 + kk * 16 + 2 * lc + 8);
        }
    }

    float oacc[8][4];
#pragma unroll
    for (int nt = 0; nt < 8; nt++)
#pragma unroll
        for (int i = 0; i < 4; i++) oacc[nt][i] = 0.f;
    float mst0 = -1e30f, mst1 = -1e30f, lst0 = 0.f, lst1 = 0.f;

    const uint32_t ks_b = smem_u32(Ksm);
    const uint32_t vs_b = smem_u32(Vsm);

    auto loadKV = [&](int n0, int st) {
#pragma unroll
        for (int i = 0; i < 2; i++) {
            int c = tid + i * 256;
            int kr = c >> 3, kc = c & 7;    // K: 64 rows x 8 chunks (128B/row)
            cp_async16(ks_b + (uint32_t)(st * KS_H + kr * AKLD + kc * 8) * 2,
                       Kbase + (size_t)(n0 + kr) * kvs + kc * 8);
            int vr = c >> 4, vc = c & 15;   // Vp: 32 rows x 16 chunks (256B/row)
            cp_async16(vs_b + (uint32_t)(st * VP_W + vr * AVLD + vc * 4) * 4,
                       Vpb + (size_t)(n0 / 2 + vr) * 64 + vc * 4);
        }
    };

    const int niter = m0 / 64 + 2;   // covers keys up to m0+127
    loadKV(0, 0);
    CP_COMMIT();

    for (int it = 0; it < niter; it++) {
        const int n0 = it * 64;
        const int st = it & 1;
        if (it + 1 < niter) {
            loadKV(n0 + 64, st ^ 1);
            CP_COMMIT();
            CP_WAIT(1);
        } else {
            CP_WAIT(0);
        }
        __syncthreads();

        const __half* Ks = Ksm[st];
        const uint32_t* Vs = Vsm[st];

        // S = Q K^T
        float s[8][4];
#pragma unroll
        for (int nt = 0; nt < 8; nt++)
#pragma unroll
            for (int i = 0; i < 4; i++) s[nt][i] = 0.f;
#pragma unroll
        for (int kk = 0; kk < 4; kk++) {
#pragma unroll
            for (int nt = 0; nt < 8; nt++) {
                uint32_t kb[2];
                const __half* p = &Ks[(nt * 8 + lr) * AKLD + kk * 16 + 2 * lc];
                kb[0] = *(const uint32_t*)(p);
                kb[1] = *(const uint32_t*)(p + 8);
                mma16n8k16(s[nt], qa[kk], kb);
            }
        }

        // causal mask (natural layout: c0,c1 = keys nt*8+2lc, +2lc+1)
        if (n0 + 63 > m0 + w * 16) {
#pragma unroll
            for (int nt = 0; nt < 8; nt++) {
                const int key0 = n0 + nt * 8 + 2 * lc;
                const int key1 = key0 + 1;
                if (key0 > row0) s[nt][0] = -1e30f;
                if (key1 > row0) s[nt][1] = -1e30f;
                if (key0 > row0 + 8) s[nt][2] = -1e30f;
                if (key1 > row0 + 8) s[nt][3] = -1e30f;
            }
        }

        // online softmax in exp2 domain (row shared by a quad)
        float mx0 = -1e30f, mx1 = -1e30f;
#pragma unroll
        for (int nt = 0; nt < 8; nt++) {
            mx0 = fmaxf(mx0, fmaxf(s[nt][0], s[nt][1]));
            mx1 = fmaxf(mx1, fmaxf(s[nt][2], s[nt][3]));
        }
        mx0 = fmaxf(mx0, __shfl_xor_sync(0xffffffffu, mx0, 1));
        mx0 = fmaxf(mx0, __shfl_xor_sync(0xffffffffu, mx0, 2));
        mx1 = fmaxf(mx1, __shfl_xor_sync(0xffffffffu, mx1, 1));
        mx1 = fmaxf(mx1, __shfl_xor_sync(0xffffffffu, mx1, 2));
        const float mn0 = fmaxf(mst0, mx0), mn1 = fmaxf(mst1, mx1);
        const float corr0 = exp2f(mst0 - mn0), corr1 = exp2f(mst1 - mn1);
        mst0 = mn0; mst1 = mn1;
        float sum0 = 0.f, sum1 = 0.f;
#pragma unroll
        for (int nt = 0; nt < 8; nt++) {
            s[nt][0] = exp2f(s[nt][0] - mn0); sum0 += s[nt][0];
            s[nt][1] = exp2f(s[nt][1] - mn0); sum0 += s[nt][1];
            s[nt][2] = exp2f(s[nt][2] - mn1); sum1 += s[nt][2];
            s[nt][3] = exp2f(s[nt][3] - mn1); sum1 += s[nt][3];
        }
        sum0 += __shfl_xor_sync(0xffffffffu, sum0, 1);
        sum0 += __shfl_xor_sync(0xffffffffu, sum0, 2);
        sum1 += __shfl_xor_sync(0xffffffffu, sum1, 1);
        sum1 += __shfl_xor_sync(0xffffffffu, sum1, 2);
        lst0 = lst0 * corr0 + sum0;
        lst1 = lst1 * corr1 + sum1;
#pragma unroll
        for (int nt = 0; nt < 8; nt++) {
            oacc[nt][0] *= corr0; oacc[nt][1] *= corr0;
            oacc[nt][2] *= corr1; oacc[nt][3] *= corr1;
        }

        // O += P V : pack S pairs directly into fp16 A-fragments
#pragma unroll
        for (int kk = 0; kk < 4; kk++) {
            uint32_t pa[4];
            pa[0] = h2pack(s[2 * kk][0], s[2 * kk][1]);
            pa[1] = h2pack(s[2 * kk][2], s[2 * kk][3]);
            pa[2] = h2pack(s[2 * kk + 1][0], s[2 * kk + 1][1]);
            pa[3] = h2pack(s[2 * kk + 1][2], s[2 * kk + 1][3]);
#pragma unroll
            for (int nt = 0; nt < 8; nt++) {
                uint32_t vb[2];
                const uint32_t* p = &Vs[(kk * 8 + lc) * AVLD + nt * 8 + lr];
                vb[0] = p[0];
                vb[1] = p[4 * AVLD];
                mma16n8k16(oacc[nt], pa, vb);
            }
        }
        __syncthreads();
    }

    const float inv0 = 1.f / lst0, inv1 = 1.f / lst1;
    __half* o0 = O + ((size_t)(b * SS + row0) * NH + h) * HD;
    __half* o1 = o0 + (size_t)8 * NH * HD;
#pragma unroll
    for (int nt = 0; nt < 8; nt++) {
        const int col = nt * 8 + lc * 2;
        *(uint32_t*)&o0[col] = h2pack(oacc[nt][0] * inv0, oacc[nt][1] * inv0);
        *(uint32_t*)&o1[col] = h2pack(oacc[nt][2] * inv1, oacc[nt][3] * inv1);
    }
}

// ---------------------------------------------------------------------------
// Launch. inputs: 0=x, 1=freqs_cos, 2=freqs_sin, 3=mask(unused),
//                 4=wq, 5=wk, 6=wv, 7=wo
// ---------------------------------------------------------------------------
extern "C" void kernel_launch(void* const* d_in, const int* in_sizes, int n_in,
                              void* d_out, int out_size)
{
    const float* x = (const float*)d_in[0];
    const float* fcos = (const float*)d_in[1];
    const float* fsin = (const float*)d_in[2];
    const float* wq = (const float*)d_in[4];
    const float* wk = (const float*)d_in[5];
    const float* wv = (const float*)d_in[6];
    const float* wo = (const float*)d_in[7];
    float* out = (float*)d_out;

    __half *xh, *wqT, *wkT, *wvT, *woT, *q, *k, *v, *att;
    uint32_t* vp;
    cudaGetSymbolAddress((void**)&xh, g_xh);
    cudaGetSymbolAddress((void**)&wqT, g_wqT);
    cudaGetSymbolAddress((void**)&wkT, g_wkT);
    cudaGetSymbolAddress((void**)&wvT, g_wvT);
    cudaGetSymbolAddress((void**)&woT, g_woT);
    cudaGetSymbolAddress((void**)&q, g_q);
    cudaGetSymbolAddress((void**)&k, g_k);
    cudaGetSymbolAddress((void**)&v, g_v);
    cudaGetSymbolAddress((void**)&att, g_att);
    cudaGetSymbolAddress((void**)&vp, g_vp);

    static bool attr_set = false;
    if (!attr_set) {
        cudaFuncSetAttribute(gemm_f16_kernel,
                             cudaFuncAttributeMaxDynamicSharedMemorySize, GEMM_SMEM);
        attr_set = true;
    }

    const int M = BB * SS;  // 4096

    // Prepass: x -> fp16; weights -> fp16 transposed [N,K]
    {
        int n4 = (BB * SS * DM) / 4;
        cvt_h_kernel<<<(n4 + 255) / 256, 256>>>((const float4*)x, (uint2*)xh, n4);
    }
    transpose_h_kernel<<<dim3((NH * HD) / 32, DM / 32), dim3(32, 8)>>>(wq, wqT, DM, NH * HD);
    transpose_h_kernel<<<dim3((NKV * HD) / 32, DM / 32), dim3(32, 8)>>>(wk, wkT, DM, NKV * HD);
    transpose_h_kernel<<<dim3((NKV * HD) / 32, DM / 32), dim3(32, 8)>>>(wv, wvT, DM, NKV * HD);
    transpose_h_kernel<<<dim3(DM / 32, DM / 32), dim3(32, 8)>>>(wo, woT, DM, DM);

    // QKV projections (fp16 mma) with fused RoPE epilogues
    gemm_f16_kernel<<<dim3((NH * HD) / 128, M / 128), 256, GEMM_SMEM>>>(
        xh, wqT, q, M, NH * HD, DM, /*mode=*/1, 0.125f * LOG2E, fcos, fsin);
    gemm_f16_kernel<<<dim3((NKV * HD) / 128, M / 128), 256, GEMM_SMEM>>>(
        xh, wkT, k, M, NKV * HD, DM, /*mode=*/2, 1.0f, fcos, fsin);
    gemm_f16_kernel<<<dim3((NKV * HD) / 128, M / 128), 256, GEMM_SMEM>>>(
        xh, wvT, v, M, NKV * HD, DM, /*mode=*/3, 1.0f, fcos, fsin);

    // Pack V into key-pair-major b32
    {
        int tot = BB * NKV * (SS / 2) * HD;
        packv_kernel<<<tot / 256, 256>>>(v, vp);
    }

    // Attention (fp16, shuffle-free PV, exp2 softmax)
    attn_kernel<<<dim3(SS / 128, NH, BB), 256>>>(q, k, vp, att);

    // Output projection (fp32 epilogue to d_out)
    gemm_f16_kernel<<<dim3(DM / 128, M / 128), 256, GEMM_SMEM>>>(
        att, woT, out, M, DM, DM, /*mode=*/0, 1.0f, fcos, fsin);
}

// round 7
// speedup vs baseline: 1.8674x; 1.0637x over previous
#include <cuda_runtime.h>
#include <cuda_fp16.h>
#include <cstdint>

// Problem constants
#define BB 2
#define SS 2048
#define DM 2048
#define NH 32
#define NKV 8
#define HD 64

#define LOG2E 1.4426950408889634f

// ---------------------------------------------------------------------------
// Scratch (allocation-free rule: __device__ globals)
// ---------------------------------------------------------------------------
__device__ __align__(1024) __half g_xh[(size_t)BB * SS * DM];
__device__ __align__(1024) __half g_wqT[(size_t)(NH * HD) * DM];
__device__ __align__(1024) __half g_wkT[(size_t)(NKV * HD) * DM];
__device__ __align__(1024) __half g_wvT[(size_t)(NKV * HD) * DM];
__device__ __align__(1024) __half g_woT[(size_t)DM * DM];
__device__ __align__(1024) __half g_q[(size_t)BB * SS * NH * HD];
__device__ __align__(1024) __half g_k[(size_t)BB * SS * NKV * HD];
__device__ __align__(1024) __half g_v[(size_t)BB * SS * NKV * HD];
__device__ __align__(1024) __half g_att[(size_t)BB * SS * NH * HD];
__device__ __align__(1024) uint32_t g_vp[(size_t)BB * NKV * (SS / 2) * HD];

// ---------------------------------------------------------------------------
// Helpers
// ---------------------------------------------------------------------------
__device__ __forceinline__ uint32_t smem_u32(const void* p) {
    uint32_t a;
    asm("{ .reg .u64 t; cvta.to.shared.u64 t, %1; cvt.u32.u64 %0, t; }" : "=r"(a) : "l"(p));
    return a;
}
// pack two fp32 -> f16x2 (lo, hi) with round-to-nearest-even
__device__ __forceinline__ uint32_t h2pack(float lo, float hi) {
    uint32_t d;
    asm("cvt.rn.f16x2.f32 %0, %1, %2;" : "=r"(d) : "f"(hi), "f"(lo));
    return d;
}
__device__ __forceinline__ void cp_async16(uint32_t smem, const void* gmem) {
    asm volatile("cp.async.cg.shared.global [%0], [%1], 16;" :: "r"(smem), "l"(gmem));
}
#define CP_COMMIT() asm volatile("cp.async.commit_group;" ::: "memory")
#define CP_WAIT(n)  asm volatile("cp.async.wait_group %0;" :: "n"(n) : "memory")

// ldmatrix x4: four 8x8 b16 matrices; lane groups 0-7/8-15/16-23/24-31 supply
// the row addresses of matrices 0..3.
__device__ __forceinline__ void ldsm_x4(uint32_t& r0, uint32_t& r1,
                                        uint32_t& r2, uint32_t& r3, uint32_t addr) {
    asm volatile("ldmatrix.sync.aligned.m8n8.x4.shared.b16 {%0,%1,%2,%3}, [%4];"
                 : "=r"(r0), "=r"(r1), "=r"(r2), "=r"(r3) : "r"(addr));
}

// m16n8k16 fp16 MMA, fp32 accumulate (sm_80+ baseline; legacy HMMA pipe)
__device__ __forceinline__ void mma16n8k16(float* d, const uint32_t* a, const uint32_t* b) {
    asm volatile(
        "mma.sync.aligned.m16n8k16.row.col.f32.f16.f16.f32 "
        "{%0,%1,%2,%3}, {%4,%5,%6,%7}, {%8,%9}, {%0,%1,%2,%3};"
        : "+f"(d[0]), "+f"(d[1]), "+f"(d[2]), "+f"(d[3])
        : "r"(a[0]), "r"(a[1]), "r"(a[2]), "r"(a[3]), "r"(b[0]), "r"(b[1]));
}

// ---------------------------------------------------------------------------
// fp16 mma.sync GEMM: C[M,N] = A[M,K] @ Bt[N,K]^T  (fp16 operands, K-major)
// BM=BN=128, BK=32, 256 threads / 8 warps (warp tile 32x64), 3-stage cp.async.
// Fragments loaded via ldmatrix.x4 (6 LDSM per k16-step vs 24 scalar LDS).
// smem rows padded to 40 halves: ldmatrix rows tile all 32 banks.
// Epilogue modes: 0 = fp32 store, 1 = rope(scale)->fp16, 2 = rope->fp16,
//                 3 = fp16 store.
// ---------------------------------------------------------------------------
#define GLD 40                 // halves per smem row
#define GAH (128 * GLD)        // halves per operand tile (5120)
#define GSTH (2 * GAH)         // halves per stage (10240)
#define GEMM_SMEM (3 * GSTH * 2)

__global__ __launch_bounds__(256) void gemm_f16_kernel(
    const __half* __restrict__ A, const __half* __restrict__ Bt,
    void* __restrict__ Cv, int M, int N, int K,
    int mode, float scale,
    const float* __restrict__ fcos, const float* __restrict__ fsin)
{
    extern __shared__ __half smh[];
    const int tid = threadIdx.x;
    const int wid = tid >> 5, lid = tid & 31;
    const int wm = wid & 3, wn = wid >> 2;       // 4x2 warp grid
    const int lr = lid >> 2, lc = lid & 3;
    const int bm = blockIdx.y * 128, bn = blockIdx.x * 128;

    const uint32_t sb = smem_u32(smh);

    // ldmatrix lane base offsets (in halves)
    const uint32_t aLane = (uint32_t)((wm * 32 + (lid & 15)) * GLD + (lid >> 4) * 8);
    const uint32_t bLane = (uint32_t)((wn * 64 + (lid & 7) + ((lid >> 4) & 1) * 8) * GLD
                                      + ((lid >> 3) & 1) * 8);

    float acc[2][8][4];
#pragma unroll
    for (int mt = 0; mt < 2; mt++)
#pragma unroll
        for (int nt = 0; nt < 8; nt++)
#pragma unroll
            for (int i = 0; i < 4; i++) acc[mt][nt][i] = 0.f;

    auto load_stage = [&](int s) {
        const int st = s - (s / 3) * 3;
        const __half* Ab = A + (size_t)bm * K + s * 32;
        const __half* Bb = Bt + (size_t)bn * K + s * 32;
#pragma unroll
        for (int i = 0; i < 2; i++) {
            int c = tid + i * 256;
            int row = c >> 2, cc = c & 3;        // 4 x 16B chunks per 32-half row
            cp_async16(sb + (uint32_t)(st * GSTH + row * GLD + cc * 8) * 2,
                       Ab + (size_t)row * K + cc * 8);
            cp_async16(sb + (uint32_t)(st * GSTH + GAH + row * GLD + cc * 8) * 2,
                       Bb + (size_t)row * K + cc * 8);
        }
    };

    const int nk = K / 32;
#pragma unroll
    for (int s = 0; s < 3; s++) { if (s < nk) load_stage(s); CP_COMMIT(); }

    for (int s = 0; s < nk; s++) {
        CP_WAIT(2);
        __syncthreads();
        const int st = s - (s / 3) * 3;
        const uint32_t sa = sb + (uint32_t)(st * GSTH) * 2;
        const uint32_t sbB = sb + (uint32_t)(st * GSTH + GAH) * 2;
#pragma unroll
        for (int kk = 0; kk < 2; kk++) {         // two k16 steps cover BK=32
            uint32_t af[2][4], bf[8][2];
#pragma unroll
            for (int mt = 0; mt < 2; mt++)
                ldsm_x4(af[mt][0], af[mt][1], af[mt][2], af[mt][3],
                        sa + (aLane + (uint32_t)(mt * 16 * GLD + kk * 16)) * 2);
#pragma unroll
            for (int p = 0; p < 4; p++)
                ldsm_x4(bf[2 * p][0], bf[2 * p][1], bf[2 * p + 1][0], bf[2 * p + 1][1],
                        sbB + (bLane + (uint32_t)(p * 16 * GLD + kk * 16)) * 2);
#pragma unroll
            for (int mt = 0; mt < 2; mt++)
#pragma unroll
                for (int nt = 0; nt < 8; nt++)
                    mma16n8k16(acc[mt][nt], af[mt], bf[nt]);
        }
        __syncthreads();
        if (s + 3 < nk) load_stage(s + 3);
        CP_COMMIT();
    }

    // epilogue
#pragma unroll
    for (int mt = 0; mt < 2; mt++) {
        const int r0 = bm + wm * 32 + mt * 16 + lr;
        const int s0 = r0 & (SS - 1);
        const int s1 = (r0 + 8) & (SS - 1);
#pragma unroll
        for (int nt = 0; nt < 8; nt++) {
            const int col = bn + wn * 64 + nt * 8 + lc * 2;
            float a0 = acc[mt][nt][0], a1 = acc[mt][nt][1];
            float a2 = acc[mt][nt][2], a3 = acc[mt][nt][3];
            if (mode == 0) {
                float* C = (float*)Cv;
                *(float2*)&C[(size_t)r0 * N + col] = make_float2(a0, a1);
                *(float2*)&C[(size_t)(r0 + 8) * N + col] = make_float2(a2, a3);
            } else if (mode == 3) {
                __half* C = (__half*)Cv;
                *(uint32_t*)&C[(size_t)r0 * N + col] = h2pack(a0, a1);
                *(uint32_t*)&C[(size_t)(r0 + 8) * N + col] = h2pack(a2, a3);
            } else {  // rope modes (pairs a0/a1 and a2/a3 are the even/odd lanes)
                const int pidx = (col & 63) >> 1;
                const float c0 = fcos[s0 * 32 + pidx], si0 = fsin[s0 * 32 + pidx];
                const float c1 = fcos[s1 * 32 + pidx], si1 = fsin[s1 * 32 + pidx];
                __half* C = (__half*)Cv;
                *(uint32_t*)&C[(size_t)r0 * N + col] =
                    h2pack(scale * (a0 * c0 - a1 * si0), scale * (a0 * si0 + a1 * c0));
                *(uint32_t*)&C[(size_t)(r0 + 8) * N + col] =
                    h2pack(scale * (a2 * c1 - a3 * si1), scale * (a2 * si1 + a3 * c1));
            }
        }
    }
}

// ---------------------------------------------------------------------------
// fp32 -> fp16 elementwise
// ---------------------------------------------------------------------------
__global__ void cvt_h_kernel(const float4* __restrict__ in,
                             uint2* __restrict__ out, int n4)
{
    int i = blockIdx.x * 256 + threadIdx.x;
    if (i >= n4) return;
    float4 v = in[i];
    uint2 o;
    o.x = h2pack(v.x, v.y);
    o.y = h2pack(v.z, v.w);
    out[i] = o;
}

// ---------------------------------------------------------------------------
// Transpose + fp16 convert: out[C,R] fp16 = in[R,C]^T
// ---------------------------------------------------------------------------
__global__ void transpose_h_kernel(const float* __restrict__ in,
                                   __half* __restrict__ out, int R, int C)
{
    __shared__ float t[32][33];
    const int bx = blockIdx.x * 32;
    const int by = blockIdx.y * 32;
    const int x = bx + threadIdx.x;
#pragma unroll
    for (int i = threadIdx.y; i < 32; i += 8)
        t[i][threadIdx.x] = in[(size_t)(by + i) * C + x];
    __syncthreads();
    const int xo = by + threadIdx.x;
#pragma unroll
    for (int i = threadIdx.y; i < 32; i += 8)
        out[(size_t)(bx + i) * R + xo] = __float2half(t[threadIdx.x][i]);
}

// ---------------------------------------------------------------------------
// Pack V into key-pair-major b32: vp[((b*NKV+kvh)*1024+sp)*64+d] =
//   { lo = V[2sp][d], hi = V[2sp+1][d] }
// ---------------------------------------------------------------------------
__global__ void packv_kernel(const __half* __restrict__ V,
                             uint32_t* __restrict__ vp)
{
    int i = blockIdx.x * 256 + threadIdx.x;   // total = BB*NKV*1024*64 = 1M
    const int d = i & 63;
    const int sp = (i >> 6) & 1023;
    const int kvh = (i >> 16) & 7;
    const int b = i >> 19;
    const size_t base = ((size_t)(b * SS + 2 * sp)) * (NKV * HD) + kvh * 64 + d;
    const uint16_t lo = __half_as_ushort(V[base]);
    const uint16_t hi = __half_as_ushort(V[base + NKV * HD]);
    vp[i] = (uint32_t)lo | ((uint32_t)hi << 16);
}

// ---------------------------------------------------------------------------
// Flash attention (causal, GQA) via mma.sync fp16 (f32 accumulate).
// Block = 128 q-rows x head x batch; 8 warps, warp owns 16 rows.
// K fragments via ldmatrix.x4. fp16 A-fragments pack adjacent column pairs ==
// S accumulator layout, so PV operand = f16x2 pack of (c0,c1)/(c2,c3): no
// shuffles. V pre-packed key-pair-major -> single-LDS32 B-frags.
// 2-stage cp.async double buffer. exp2 domain (log2e folded into q scale).
// ---------------------------------------------------------------------------
#define AKLD 72      // halves per K row (64 + pad) -> 36-word stride
#define AVLD 72      // words per Vp row (64 + pad)
#define KS_H (64 * AKLD)
#define VP_W (32 * AVLD)

__global__ __launch_bounds__(256, 2) void attn_kernel(
    const __half* __restrict__ Q, const __half* __restrict__ Kg,
    const uint32_t* __restrict__ Vp, __half* __restrict__ O)
{
    __shared__ __align__(16) __half Ksm[2][KS_H];
    __shared__ __align__(16) uint32_t Vsm[2][VP_W];

    const int tile = gridDim.x - 1 - blockIdx.x;   // heavy tiles first
    const int m0 = tile * 128;
    const int h = blockIdx.y;
    const int b = blockIdx.z;
    const int kvh = h >> 2;
    const int tid = threadIdx.x;
    const int w = tid >> 5, lid = tid & 31;
    const int lr = lid >> 2, lc = lid & 3;
    const int row0 = m0 + w * 16 + lr;   // second row-half is row0+8

    const int kvs = NKV * HD;  // 512
    const __half* Kbase = Kg + (size_t)b * SS * kvs + kvh * 64;
    const uint32_t* Vpb = Vp + ((size_t)(b * NKV + kvh) * (SS / 2)) * 64;

    // ldmatrix lane base offset for K fragments (in halves)
    const uint32_t kLane = (uint32_t)(((lid & 7) + ((lid >> 4) & 1) * 8) * AKLD
                                      + ((lid >> 3) & 1) * 8);

    // Persistent Q fragments (q has 0.125*log2e folded in, fp16)
    uint32_t qa[4][4];
    {
        const __half* q0 = Q + ((size_t)(b * SS + row0) * NH + h) * HD;
        const __half* q1 = q0 + (size_t)8 * NH * HD;
#pragma unroll
        for (int kk = 0; kk < 4; kk++) {
            qa[kk][0] = *(const uint32_t*)(q0 + kk * 16 + 2 * lc);
            qa[kk][1] = *(const uint32_t*)(q1 + kk * 16 + 2 * lc);
            qa[kk][2] = *(const uint32_t*)(q0 + kk * 16 + 2 * lc + 8);
            qa[kk][3] = *(const uint32_t*)(q1 + kk * 16 + 2 * lc + 8);
        }
    }

    float oacc[8][4];
#pragma unroll
    for (int nt = 0; nt < 8; nt++)
#pragma unroll
        for (int i = 0; i < 4; i++) oacc[nt][i] = 0.f;
    float mst0 = -1e30f, mst1 = -1e30f, lst0 = 0.f, lst1 = 0.f;

    const uint32_t ks_b = smem_u32(Ksm);
    const uint32_t vs_b = smem_u32(Vsm);

    auto loadKV = [&](int n0, int st) {
#pragma unroll
        for (int i = 0; i < 2; i++) {
            int c = tid + i * 256;
            int kr = c >> 3, kc = c & 7;    // K: 64 rows x 8 chunks (128B/row)
            cp_async16(ks_b + (uint32_t)(st * KS_H + kr * AKLD + kc * 8) * 2,
                       Kbase + (size_t)(n0 + kr) * kvs + kc * 8);
            int vr = c >> 4, vc = c & 15;   // Vp: 32 rows x 16 chunks (256B/row)
            cp_async16(vs_b + (uint32_t)(st * VP_W + vr * AVLD + vc * 4) * 4,
                       Vpb + (size_t)(n0 / 2 + vr) * 64 + vc * 4);
        }
    };

    const int niter = m0 / 64 + 2;   // covers keys up to m0+127
    loadKV(0, 0);
    CP_COMMIT();

    for (int it = 0; it < niter; it++) {
        const int n0 = it * 64;
        const int st = it & 1;
        if (it + 1 < niter) {
            loadKV(n0 + 64, st ^ 1);
            CP_COMMIT();
            CP_WAIT(1);
        } else {
            CP_WAIT(0);
        }
        __syncthreads();

        const uint32_t ksa = ks_b + (uint32_t)(st * KS_H) * 2;
        const uint32_t* Vs = Vsm[st];

        // S = Q K^T (K fragments via ldmatrix.x4)
        float s[8][4];
#pragma unroll
        for (int nt = 0; nt < 8; nt++)
#pragma unroll
            for (int i = 0; i < 4; i++) s[nt][i] = 0.f;
#pragma unroll
        for (int kk = 0; kk < 4; kk++) {
            uint32_t kb[8][2];
#pragma unroll
            for (int p = 0; p < 4; p++)
                ldsm_x4(kb[2 * p][0], kb[2 * p][1], kb[2 * p + 1][0], kb[2 * p + 1][1],
                        ksa + (kLane + (uint32_t)(p * 16 * AKLD + kk * 16)) * 2);
#pragma unroll
            for (int nt = 0; nt < 8; nt++)
                mma16n8k16(s[nt], qa[kk], kb[nt]);
        }

        // causal mask (c0,c1 = keys nt*8+2lc, +2lc+1)
        if (n0 + 63 > m0 + w * 16) {
#pragma unroll
            for (int nt = 0; nt < 8; nt++) {
                const int key0 = n0 + nt * 8 + 2 * lc;
                const int key1 = key0 + 1;
                if (key0 > row0) s[nt][0] = -1e30f;
                if (key1 > row0) s[nt][1] = -1e30f;
                if (key0 > row0 + 8) s[nt][2] = -1e30f;
                if (key1 > row0 + 8) s[nt][3] = -1e30f;
            }
        }

        // online softmax in exp2 domain (row shared by a quad)
        float mx0 = -1e30f, mx1 = -1e30f;
#pragma unroll
        for (int nt = 0; nt < 8; nt++) {
            mx0 = fmaxf(mx0, fmaxf(s[nt][0], s[nt][1]));
            mx1 = fmaxf(mx1, fmaxf(s[nt][2], s[nt][3]));
        }
        mx0 = fmaxf(mx0, __shfl_xor_sync(0xffffffffu, mx0, 1));
        mx0 = fmaxf(mx0, __shfl_xor_sync(0xffffffffu, mx0, 2));
        mx1 = fmaxf(mx1, __shfl_xor_sync(0xffffffffu, mx1, 1));
        mx1 = fmaxf(mx1, __shfl_xor_sync(0xffffffffu, mx1, 2));
        const float mn0 = fmaxf(mst0, mx0), mn1 = fmaxf(mst1, mx1);
        const float corr0 = exp2f(mst0 - mn0), corr1 = exp2f(mst1 - mn1);
        mst0 = mn0; mst1 = mn1;
        float sum0 = 0.f, sum1 = 0.f;
#pragma unroll
        for (int nt = 0; nt < 8; nt++) {
            s[nt][0] = exp2f(s[nt][0] - mn0); sum0 += s[nt][0];
            s[nt][1] = exp2f(s[nt][1] - mn0); sum0 += s[nt][1];
            s[nt][2] = exp2f(s[nt][2] - mn1); sum1 += s[nt][2];
            s[nt][3] = exp2f(s[nt][3] - mn1); sum1 += s[nt][3];
        }
        sum0 += __shfl_xor_sync(0xffffffffu, sum0, 1);
        sum0 += __shfl_xor_sync(0xffffffffu, sum0, 2);
        sum1 += __shfl_xor_sync(0xffffffffu, sum1, 1);
        sum1 += __shfl_xor_sync(0xffffffffu, sum1, 2);
        lst0 = lst0 * corr0 + sum0;
        lst1 = lst1 * corr1 + sum1;
#pragma unroll
        for (int nt = 0; nt < 8; nt++) {
            oacc[nt][0] *= corr0; oacc[nt][1] *= corr0;
            oacc[nt][2] *= corr1; oacc[nt][3] *= corr1;
        }

        // O += P V : pack S pairs directly into fp16 A-fragments
#pragma unroll
        for (int kk = 0; kk < 4; kk++) {
            uint32_t pa[4];
            pa[0] = h2pack(s[2 * kk][0], s[2 * kk][1]);
            pa[1] = h2pack(s[2 * kk][2], s[2 * kk][3]);
            pa[2] = h2pack(s[2 * kk + 1][0], s[2 * kk + 1][1]);
            pa[3] = h2pack(s[2 * kk + 1][2], s[2 * kk + 1][3]);
#pragma unroll
            for (int nt = 0; nt < 8; nt++) {
                uint32_t vb[2];
                const uint32_t* p = &Vs[(kk * 8 + lc) * AVLD + nt * 8 + lr];
                vb[0] = p[0];
                vb[1] = p[4 * AVLD];
                mma16n8k16(oacc[nt], pa, vb);
            }
        }
        __syncthreads();
    }

    const float inv0 = 1.f / lst0, inv1 = 1.f / lst1;
    __half* o0 = O + ((size_t)(b * SS + row0) * NH + h) * HD;
    __half* o1 = o0 + (size_t)8 * NH * HD;
#pragma unroll
    for (int nt = 0; nt < 8; nt++) {
        const int col = nt * 8 + lc * 2;
        *(uint32_t*)&o0[col] = h2pack(oacc[nt][0] * inv0, oacc[nt][1] * inv0);
        *(uint32_t*)&o1[col] = h2pack(oacc[nt][2] * inv1, oacc[nt][3] * inv1);
    }
}

// ---------------------------------------------------------------------------
// Launch. inputs: 0=x, 1=freqs_cos, 2=freqs_sin, 3=mask(unused),
//                 4=wq, 5=wk, 6=wv, 7=wo
// ---------------------------------------------------------------------------
extern "C" void kernel_launch(void* const* d_in, const int* in_sizes, int n_in,
                              void* d_out, int out_size)
{
    const float* x = (const float*)d_in[0];
    const float* fcos = (const float*)d_in[1];
    const float* fsin = (const float*)d_in[2];
    const float* wq = (const float*)d_in[4];
    const float* wk = (const float*)d_in[5];
    const float* wv = (const float*)d_in[6];
    const float* wo = (const float*)d_in[7];
    float* out = (float*)d_out;

    __half *xh, *wqT, *wkT, *wvT, *woT, *q, *k, *v, *att;
    uint32_t* vp;
    cudaGetSymbolAddress((void**)&xh, g_xh);
    cudaGetSymbolAddress((void**)&wqT, g_wqT);
    cudaGetSymbolAddress((void**)&wkT, g_wkT);
    cudaGetSymbolAddress((void**)&wvT, g_wvT);
    cudaGetSymbolAddress((void**)&woT, g_woT);
    cudaGetSymbolAddress((void**)&q, g_q);
    cudaGetSymbolAddress((void**)&k, g_k);
    cudaGetSymbolAddress((void**)&v, g_v);
    cudaGetSymbolAddress((void**)&att, g_att);
    cudaGetSymbolAddress((void**)&vp, g_vp);

    static bool attr_set = false;
    if (!attr_set) {
        cudaFuncSetAttribute(gemm_f16_kernel,
                             cudaFuncAttributeMaxDynamicSharedMemorySize, GEMM_SMEM);
        attr_set = true;
    }

    const int M = BB * SS;  // 4096

    // Prepass: x -> fp16; weights -> fp16 transposed [N,K]
    {
        int n4 = (BB * SS * DM) / 4;
        cvt_h_kernel<<<(n4 + 255) / 256, 256>>>((const float4*)x, (uint2*)xh, n4);
    }
    transpose_h_kernel<<<dim3((NH * HD) / 32, DM / 32), dim3(32, 8)>>>(wq, wqT, DM, NH * HD);
    transpose_h_kernel<<<dim3((NKV * HD) / 32, DM / 32), dim3(32, 8)>>>(wk, wkT, DM, NKV * HD);
    transpose_h_kernel<<<dim3((NKV * HD) / 32, DM / 32), dim3(32, 8)>>>(wv, wvT, DM, NKV * HD);
    transpose_h_kernel<<<dim3(DM / 32, DM / 32), dim3(32, 8)>>>(wo, woT, DM, DM);

    // QKV projections (fp16 mma, ldmatrix frags) with fused RoPE epilogues
    gemm_f16_kernel<<<dim3((NH * HD) / 128, M / 128), 256, GEMM_SMEM>>>(
        xh, wqT, q, M, NH * HD, DM, /*mode=*/1, 0.125f * LOG2E, fcos, fsin);
    gemm_f16_kernel<<<dim3((NKV * HD) / 128, M / 128), 256, GEMM_SMEM>>>(
        xh, wkT, k, M, NKV * HD, DM, /*mode=*/2, 1.0f, fcos, fsin);
    gemm_f16_kernel<<<dim3((NKV * HD) / 128, M / 128), 256, GEMM_SMEM>>>(
        xh, wvT, v, M, NKV * HD, DM, /*mode=*/3, 1.0f, fcos, fsin);

    // Pack V into key-pair-major b32
    {
        int tot = BB * NKV * (SS / 2) * HD;
        packv_kernel<<<tot / 256, 256>>>(v, vp);
    }

    // Attention (fp16, ldmatrix K-frags, shuffle-free PV, exp2 softmax)
    attn_kernel<<<dim3(SS / 128, NH, BB), 256>>>(q, k, vp, att);

    // Output projection (fp32 epilogue to d_out)
    gemm_f16_kernel<<<dim3(DM / 128, M / 128), 256, GEMM_SMEM>>>(
        att, woT, out, M, DM, DM, /*mode=*/0, 1.0f, fcos, fsin);
}

// round 8
// speedup vs baseline: 1.9998x; 1.0709x over previous
#include <cuda_runtime.h>
#include <cuda_fp16.h>
#include <cstdint>

// Problem constants
#define BB 2
#define SS 2048
#define DM 2048
#define NH 32
#define NKV 8
#define HD 64

#define LOG2E 1.4426950408889634f
#define NQKV (NH * HD + 2 * NKV * HD)   // 3072 concatenated output cols

// ---------------------------------------------------------------------------
// Scratch (allocation-free rule: __device__ globals)
// ---------------------------------------------------------------------------
__device__ __align__(1024) __half g_xh[(size_t)BB * SS * DM];
__device__ __align__(1024) __half g_wqkvT[(size_t)NQKV * DM];  // [3072, 2048]
__device__ __align__(1024) __half g_woT[(size_t)DM * DM];
__device__ __align__(1024) __half g_q[(size_t)BB * SS * NH * HD];
__device__ __align__(1024) __half g_k[(size_t)BB * SS * NKV * HD];
__device__ __align__(1024) __half g_v[(size_t)BB * SS * NKV * HD];
__device__ __align__(1024) __half g_att[(size_t)BB * SS * NH * HD];
__device__ __align__(1024) uint32_t g_vp[(size_t)BB * NKV * (SS / 2) * HD];

// ---------------------------------------------------------------------------
// Helpers
// ---------------------------------------------------------------------------
__device__ __forceinline__ uint32_t smem_u32(const void* p) {
    uint32_t a;
    asm("{ .reg .u64 t; cvta.to.shared.u64 t, %1; cvt.u32.u64 %0, t; }" : "=r"(a) : "l"(p));
    return a;
}
// pack two fp32 -> f16x2 (lo, hi) with round-to-nearest-even
__device__ __forceinline__ uint32_t h2pack(float lo, float hi) {
    uint32_t d;
    asm("cvt.rn.f16x2.f32 %0, %1, %2;" : "=r"(d) : "f"(hi), "f"(lo));
    return d;
}
__device__ __forceinline__ void cp_async16(uint32_t smem, const void* gmem) {
    asm volatile("cp.async.cg.shared.global [%0], [%1], 16;" :: "r"(smem), "l"(gmem));
}
#define CP_COMMIT() asm volatile("cp.async.commit_group;" ::: "memory")
#define CP_WAIT(n)  asm volatile("cp.async.wait_group %0;" :: "n"(n) : "memory")

// ldmatrix x4: four 8x8 b16 matrices
__device__ __forceinline__ void ldsm_x4(uint32_t& r0, uint32_t& r1,
                                        uint32_t& r2, uint32_t& r3, uint32_t addr) {
    asm volatile("ldmatrix.sync.aligned.m8n8.x4.shared.b16 {%0,%1,%2,%3}, [%4];"
                 : "=r"(r0), "=r"(r1), "=r"(r2), "=r"(r3) : "r"(addr));
}

// m16n8k16 fp16 MMA, fp32 accumulate (sm_80+ baseline; legacy HMMA pipe)
__device__ __forceinline__ void mma16n8k16(float* d, const uint32_t* a, const uint32_t* b) {
    asm volatile(
        "mma.sync.aligned.m16n8k16.row.col.f32.f16.f16.f32 "
        "{%0,%1,%2,%3}, {%4,%5,%6,%7}, {%8,%9}, {%0,%1,%2,%3};"
        : "+f"(d[0]), "+f"(d[1]), "+f"(d[2]), "+f"(d[3])
        : "r"(a[0]), "r"(a[1]), "r"(a[2]), "r"(a[3]), "r"(b[0]), "r"(b[1]));
}

// ---------------------------------------------------------------------------
// fp16 mma.sync GEMM: C = A[M,K] @ Bt[N,K]^T (fp16, K-major), ldmatrix frags.
// BM=BN=128, BK=32, 256 threads / 8 warps (warp tile 32x64), 3-stage cp.async,
// 2 blocks/SM. Epilogue modes: 0 = fp32 store to Cv; -1 = fused QKV: segment
// decided per block from bn (q: rope+scale -> qd, k: rope -> kd, v: fp16 -> vd).
// ---------------------------------------------------------------------------
#define GLD 40                 // halves per smem row
#define GAH (128 * GLD)        // halves per operand tile (5120)
#define GSTH (2 * GAH)         // halves per stage (10240)
#define GEMM_SMEM (3 * GSTH * 2)

__global__ __launch_bounds__(256, 2) void gemm_f16_kernel(
    const __half* __restrict__ A, const __half* __restrict__ Bt,
    void* __restrict__ Cv, int M, int N, int K, int mode,
    __half* __restrict__ qd, __half* __restrict__ kd, __half* __restrict__ vd,
    const float* __restrict__ fcos, const float* __restrict__ fsin)
{
    extern __shared__ __half smh[];
    const int tid = threadIdx.x;
    const int wid = tid >> 5, lid = tid & 31;
    const int wm = wid & 3, wn = wid >> 2;       // 4x2 warp grid
    const int lr = lid >> 2, lc = lid & 3;
    const int bm = blockIdx.y * 128, bn = blockIdx.x * 128;

    const uint32_t sb = smem_u32(smh);

    // ldmatrix lane base offsets (in halves)
    const uint32_t aLane = (uint32_t)((wm * 32 + (lid & 15)) * GLD + (lid >> 4) * 8);
    const uint32_t bLane = (uint32_t)((wn * 64 + (lid & 7) + ((lid >> 4) & 1) * 8) * GLD
                                      + ((lid >> 3) & 1) * 8);

    float acc[2][8][4];
#pragma unroll
    for (int mt = 0; mt < 2; mt++)
#pragma unroll
        for (int nt = 0; nt < 8; nt++)
#pragma unroll
            for (int i = 0; i < 4; i++) acc[mt][nt][i] = 0.f;

    auto load_stage = [&](int s) {
        const int st = s - (s / 3) * 3;
        const __half* Ab = A + (size_t)bm * K + s * 32;
        const __half* Bb = Bt + (size_t)bn * K + s * 32;
#pragma unroll
        for (int i = 0; i < 2; i++) {
            int c = tid + i * 256;
            int row = c >> 2, cc = c & 3;        // 4 x 16B chunks per 32-half row
            cp_async16(sb + (uint32_t)(st * GSTH + row * GLD + cc * 8) * 2,
                       Ab + (size_t)row * K + cc * 8);
            cp_async16(sb + (uint32_t)(st * GSTH + GAH + row * GLD + cc * 8) * 2,
                       Bb + (size_t)row * K + cc * 8);
        }
    };

    const int nk = K / 32;
#pragma unroll
    for (int s = 0; s < 3; s++) { if (s < nk) load_stage(s); CP_COMMIT(); }

    for (int s = 0; s < nk; s++) {
        CP_WAIT(2);
        __syncthreads();
        const int st = s - (s / 3) * 3;
        const uint32_t sa = sb + (uint32_t)(st * GSTH) * 2;
        const uint32_t sbB = sb + (uint32_t)(st * GSTH + GAH) * 2;
#pragma unroll
        for (int kk = 0; kk < 2; kk++) {         // two k16 steps cover BK=32
            uint32_t af[2][4], bf[8][2];
#pragma unroll
            for (int mt = 0; mt < 2; mt++)
                ldsm_x4(af[mt][0], af[mt][1], af[mt][2], af[mt][3],
                        sa + (aLane + (uint32_t)(mt * 16 * GLD + kk * 16)) * 2);
#pragma unroll
            for (int p = 0; p < 4; p++)
                ldsm_x4(bf[2 * p][0], bf[2 * p][1], bf[2 * p + 1][0], bf[2 * p + 1][1],
                        sbB + (bLane + (uint32_t)(p * 16 * GLD + kk * 16)) * 2);
#pragma unroll
            for (int mt = 0; mt < 2; mt++)
#pragma unroll
                for (int nt = 0; nt < 8; nt++)
                    mma16n8k16(acc[mt][nt], af[mt], bf[nt]);
        }
        __syncthreads();
        if (s + 3 < nk) load_stage(s + 3);
        CP_COMMIT();
    }

    // epilogue: resolve destination segment (uniform per block)
    int emode = mode;
    void* dst = Cv;
    int Nd = N, colb = bn;
    float scale = 1.0f;
    if (mode < 0) {
        if (bn < NH * HD)            { emode = 1; dst = qd; Nd = NH * HD;  colb = bn;
                                       scale = 0.125f * LOG2E; }
        else if (bn < NH * HD + NKV * HD) { emode = 2; dst = kd; Nd = NKV * HD;
                                       colb = bn - NH * HD; }
        else                          { emode = 3; dst = vd; Nd = NKV * HD;
                                       colb = bn - NH * HD - NKV * HD; }
    }

#pragma unroll
    for (int mt = 0; mt < 2; mt++) {
        const int r0 = bm + wm * 32 + mt * 16 + lr;
        const int s0 = r0 & (SS - 1);
        const int s1 = (r0 + 8) & (SS - 1);
#pragma unroll
        for (int nt = 0; nt < 8; nt++) {
            const int col = colb + wn * 64 + nt * 8 + lc * 2;
            float a0 = acc[mt][nt][0], a1 = acc[mt][nt][1];
            float a2 = acc[mt][nt][2], a3 = acc[mt][nt][3];
            if (emode == 0) {
                float* C = (float*)dst;
                *(float2*)&C[(size_t)r0 * Nd + col] = make_float2(a0, a1);
                *(float2*)&C[(size_t)(r0 + 8) * Nd + col] = make_float2(a2, a3);
            } else if (emode == 3) {
                __half* C = (__half*)dst;
                *(uint32_t*)&C[(size_t)r0 * Nd + col] = h2pack(a0, a1);
                *(uint32_t*)&C[(size_t)(r0 + 8) * Nd + col] = h2pack(a2, a3);
            } else {  // rope (a0/a1 and a2/a3 are the even/odd rotation pairs)
                const int pidx = (col & 63) >> 1;
                const float c0 = fcos[s0 * 32 + pidx], si0 = fsin[s0 * 32 + pidx];
                const float c1 = fcos[s1 * 32 + pidx], si1 = fsin[s1 * 32 + pidx];
                const float sc = (emode == 1) ? scale : 1.0f;
                __half* C = (__half*)dst;
                *(uint32_t*)&C[(size_t)r0 * Nd + col] =
                    h2pack(sc * (a0 * c0 - a1 * si0), sc * (a0 * si0 + a1 * c0));
                *(uint32_t*)&C[(size_t)(r0 + 8) * Nd + col] =
                    h2pack(sc * (a2 * c1 - a3 * si1), sc * (a2 * si1 + a3 * c1));
            }
        }
    }
}

// ---------------------------------------------------------------------------
// fp32 -> fp16 elementwise
// ---------------------------------------------------------------------------
__global__ void cvt_h_kernel(const float4* __restrict__ in,
                             uint2* __restrict__ out, int n4)
{
    int i = blockIdx.x * 256 + threadIdx.x;
    if (i >= n4) return;
    float4 v = in[i];
    uint2 o;
    o.x = h2pack(v.x, v.y);
    o.y = h2pack(v.z, v.w);
    out[i] = o;
}

// ---------------------------------------------------------------------------
// Transpose + fp16 convert: out[C,R] fp16 = in[R,C]^T
// ---------------------------------------------------------------------------
__global__ void transpose_h_kernel(const float* __restrict__ in,
                                   __half* __restrict__ out, int R, int C)
{
    __shared__ float t[32][33];
    const int bx = blockIdx.x * 32;
    const int by = blockIdx.y * 32;
    const int x = bx + threadIdx.x;
#pragma unroll
    for (int i = threadIdx.y; i < 32; i += 8)
        t[i][threadIdx.x] = in[(size_t)(by + i) * C + x];
    __syncthreads();
    const int xo = by + threadIdx.x;
#pragma unroll
    for (int i = threadIdx.y; i < 32; i += 8)
        out[(size_t)(bx + i) * R + xo] = __float2half(t[threadIdx.x][i]);
}

// ---------------------------------------------------------------------------
// Pack V into key-pair-major b32
// ---------------------------------------------------------------------------
__global__ void packv_kernel(const __half* __restrict__ V,
                             uint32_t* __restrict__ vp)
{
    int i = blockIdx.x * 256 + threadIdx.x;   // total = BB*NKV*1024*64 = 1M
    const int d = i & 63;
    const int sp = (i >> 6) & 1023;
    const int kvh = (i >> 16) & 7;
    const int b = i >> 19;
    const size_t base = ((size_t)(b * SS + 2 * sp)) * (NKV * HD) + kvh * 64 + d;
    const uint16_t lo = __half_as_ushort(V[base]);
    const uint16_t hi = __half_as_ushort(V[base + NKV * HD]);
    vp[i] = (uint32_t)lo | ((uint32_t)hi << 16);
}

// ---------------------------------------------------------------------------
// Flash attention (causal, GQA) via mma.sync fp16 (f32 accumulate).
// Block = 128 q-rows x head x batch; 8 warps, warp owns 16 rows.
// K frags via ldmatrix.x4; PV A-frags = f16x2 packs of the S accumulator (no
// shuffles); V pre-packed key-pair-major -> single-LDS32 B-frags.
// 2-stage cp.async double buffer. exp2 domain (log2e folded into q scale).
// ---------------------------------------------------------------------------
#define AKLD 72      // halves per K row (64 + pad) -> 36-word stride
#define AVLD 72      // words per Vp row (64 + pad)
#define KS_H (64 * AKLD)
#define VP_W (32 * AVLD)

__global__ __launch_bounds__(256, 2) void attn_kernel(
    const __half* __restrict__ Q, const __half* __restrict__ Kg,
    const uint32_t* __restrict__ Vp, __half* __restrict__ O)
{
    __shared__ __align__(16) __half Ksm[2][KS_H];
    __shared__ __align__(16) uint32_t Vsm[2][VP_W];

    const int tile = gridDim.x - 1 - blockIdx.x;   // heavy tiles first
    const int m0 = tile * 128;
    const int h = blockIdx.y;
    const int b = blockIdx.z;
    const int kvh = h >> 2;
    const int tid = threadIdx.x;
    const int w = tid >> 5, lid = tid & 31;
    const int lr = lid >> 2, lc = lid & 3;
    const int row0 = m0 + w * 16 + lr;

    const int kvs = NKV * HD;  // 512
    const __half* Kbase = Kg + (size_t)b * SS * kvs + kvh * 64;
    const uint32_t* Vpb = Vp + ((size_t)(b * NKV + kvh) * (SS / 2)) * 64;

    const uint32_t kLane = (uint32_t)(((lid & 7) + ((lid >> 4) & 1) * 8) * AKLD
                                      + ((lid >> 3) & 1) * 8);

    // Persistent Q fragments (q has 0.125*log2e folded in, fp16)
    uint32_t qa[4][4];
    {
        const __half* q0 = Q + ((size_t)(b * SS + row0) * NH + h) * HD;
        const __half* q1 = q0 + (size_t)8 * NH * HD;
#pragma unroll
        for (int kk = 0; kk < 4; kk++) {
            qa[kk][0] = *(const uint32_t*)(q0 + kk * 16 + 2 * lc);
            qa[kk][1] = *(const uint32_t*)(q1 + kk * 16 + 2 * lc);
            qa[kk][2] = *(const uint32_t*)(q0 + kk * 16 + 2 * lc + 8);
            qa[kk][3] = *(const uint32_t*)(q1 + kk * 16 + 2 * lc + 8);
        }
    }

    float oacc[8][4];
#pragma unroll
    for (int nt = 0; nt < 8; nt++)
#pragma unroll
        for (int i = 0; i < 4; i++) oacc[nt][i] = 0.f;
    float mst0 = -1e30f, mst1 = -1e30f, lst0 = 0.f, lst1 = 0.f;

    const uint32_t ks_b = smem_u32(Ksm);
    const uint32_t vs_b = smem_u32(Vsm);

    auto loadKV = [&](int n0, int st) {
#pragma unroll
        for (int i = 0; i < 2; i++) {
            int c = tid + i * 256;
            int kr = c >> 3, kc = c & 7;
            cp_async16(ks_b + (uint32_t)(st * KS_H + kr * AKLD + kc * 8) * 2,
                       Kbase + (size_t)(n0 + kr) * kvs + kc * 8);
            int vr = c >> 4, vc = c & 15;
            cp_async16(vs_b + (uint32_t)(st * VP_W + vr * AVLD + vc * 4) * 4,
                       Vpb + (size_t)(n0 / 2 + vr) * 64 + vc * 4);
        }
    };

    const int niter = m0 / 64 + 2;
    loadKV(0, 0);
    CP_COMMIT();

    for (int it = 0; it < niter; it++) {
        const int n0 = it * 64;
        const int st = it & 1;
        if (it + 1 < niter) {
            loadKV(n0 + 64, st ^ 1);
            CP_COMMIT();
            CP_WAIT(1);
        } else {
            CP_WAIT(0);
        }
        __syncthreads();

        const uint32_t ksa = ks_b + (uint32_t)(st * KS_H) * 2;
        const uint32_t* Vs = Vsm[st];

        float s[8][4];
#pragma unroll
        for (int nt = 0; nt < 8; nt++)
#pragma unroll
            for (int i = 0; i < 4; i++) s[nt][i] = 0.f;
#pragma unroll
        for (int kk = 0; kk < 4; kk++) {
            uint32_t kb[8][2];
#pragma unroll
            for (int p = 0; p < 4; p++)
                ldsm_x4(kb[2 * p][0], kb[2 * p][1], kb[2 * p + 1][0], kb[2 * p + 1][1],
                        ksa + (kLane + (uint32_t)(p * 16 * AKLD + kk * 16)) * 2);
#pragma unroll
            for (int nt = 0; nt < 8; nt++)
                mma16n8k16(s[nt], qa[kk], kb[nt]);
        }

        if (n0 + 63 > m0 + w * 16) {
#pragma unroll
            for (int nt = 0; nt < 8; nt++) {
                const int key0 = n0 + nt * 8 + 2 * lc;
                const int key1 = key0 + 1;
                if (key0 > row0) s[nt][0] = -1e30f;
                if (key1 > row0) s[nt][1] = -1e30f;
                if (key0 > row0 + 8) s[nt][2] = -1e30f;
                if (key1 > row0 + 8) s[nt][3] = -1e30f;
            }
        }

        float mx0 = -1e30f, mx1 = -1e30f;
#pragma unroll
        for (int nt = 0; nt < 8; nt++) {
            mx0 = fmaxf(mx0, fmaxf(s[nt][0], s[nt][1]));
            mx1 = fmaxf(mx1, fmaxf(s[nt][2], s[nt][3]));
        }
        mx0 = fmaxf(mx0, __shfl_xor_sync(0xffffffffu, mx0, 1));
        mx0 = fmaxf(mx0, __shfl_xor_sync(0xffffffffu, mx0, 2));
        mx1 = fmaxf(mx1, __shfl_xor_sync(0xffffffffu, mx1, 1));
        mx1 = fmaxf(mx1, __shfl_xor_sync(0xffffffffu, mx1, 2));
        const float mn0 = fmaxf(mst0, mx0), mn1 = fmaxf(mst1, mx1);
        const float corr0 = exp2f(mst0 - mn0), corr1 = exp2f(mst1 - mn1);
        mst0 = mn0; mst1 = mn1;
        float sum0 = 0.f, sum1 = 0.f;
#pragma unroll
        for (int nt = 0; nt < 8; nt++) {
            s[nt][0] = exp2f(s[nt][0] - mn0); sum0 += s[nt][0];
            s[nt][1] = exp2f(s[nt][1] - mn0); sum0 += s[nt][1];
            s[nt][2] = exp2f(s[nt][2] - mn1); sum1 += s[nt][2];
            s[nt][3] = exp2f(s[nt][3] - mn1); sum1 += s[nt][3];
        }
        sum0 += __shfl_xor_sync(0xffffffffu, sum0, 1);
        sum0 += __shfl_xor_sync(0xffffffffu, sum0, 2);
        sum1 += __shfl_xor_sync(0xffffffffu, sum1, 1);
        sum1 += __shfl_xor_sync(0xffffffffu, sum1, 2);
        lst0 = lst0 * corr0 + sum0;
        lst1 = lst1 * corr1 + sum1;
#pragma unroll
        for (int nt = 0; nt < 8; nt++) {
            oacc[nt][0] *= corr0; oacc[nt][1] *= corr0;
            oacc[nt][2] *= corr1; oacc[nt][3] *= corr1;
        }

#pragma unroll
        for (int kk = 0; kk < 4; kk++) {
            uint32_t pa[4];
            pa[0] = h2pack(s[2 * kk][0], s[2 * kk][1]);
            pa[1] = h2pack(s[2 * kk][2], s[2 * kk][3]);
            pa[2] = h2pack(s[2 * kk + 1][0], s[2 * kk + 1][1]);
            pa[3] = h2pack(s[2 * kk + 1][2], s[2 * kk + 1][3]);
#pragma unroll
            for (int nt = 0; nt < 8; nt++) {
                uint32_t vb[2];
                const uint32_t* p = &Vs[(kk * 8 + lc) * AVLD + nt * 8 + lr];
                vb[0] = p[0];
                vb[1] = p[4 * AVLD];
                mma16n8k16(oacc[nt], pa, vb);
            }
        }
        __syncthreads();
    }

    const float inv0 = 1.f / lst0, inv1 = 1.f / lst1;
    __half* o0 = O + ((size_t)(b * SS + row0) * NH + h) * HD;
    __half* o1 = o0 + (size_t)8 * NH * HD;
#pragma unroll
    for (int nt = 0; nt < 8; nt++) {
        const int col = nt * 8 + lc * 2;
        *(uint32_t*)&o0[col] = h2pack(oacc[nt][0] * inv0, oacc[nt][1] * inv0);
        *(uint32_t*)&o1[col] = h2pack(oacc[nt][2] * inv1, oacc[nt][3] * inv1);
    }
}

// ---------------------------------------------------------------------------
// Launch. inputs: 0=x, 1=freqs_cos, 2=freqs_sin, 3=mask(unused),
//                 4=wq, 5=wk, 6=wv, 7=wo
// ---------------------------------------------------------------------------
extern "C" void kernel_launch(void* const* d_in, const int* in_sizes, int n_in,
                              void* d_out, int out_size)
{
    const float* x = (const float*)d_in[0];
    const float* fcos = (const float*)d_in[1];
    const float* fsin = (const float*)d_in[2];
    const float* wq = (const float*)d_in[4];
    const float* wk = (const float*)d_in[5];
    const float* wv = (const float*)d_in[6];
    const float* wo = (const float*)d_in[7];
    float* out = (float*)d_out;

    __half *xh, *wqkvT, *woT, *q, *k, *v, *att;
    uint32_t* vp;
    cudaGetSymbolAddress((void**)&xh, g_xh);
    cudaGetSymbolAddress((void**)&wqkvT, g_wqkvT);
    cudaGetSymbolAddress((void**)&woT, g_woT);
    cudaGetSymbolAddress((void**)&q, g_q);
    cudaGetSymbolAddress((void**)&k, g_k);
    cudaGetSymbolAddress((void**)&v, g_v);
    cudaGetSymbolAddress((void**)&att, g_att);
    cudaGetSymbolAddress((void**)&vp, g_vp);

    static bool attr_set = false;
    if (!attr_set) {
        cudaFuncSetAttribute(gemm_f16_kernel,
                             cudaFuncAttributeMaxDynamicSharedMemorySize, GEMM_SMEM);
        attr_set = true;
    }

    const int M = BB * SS;  // 4096

    // Prepass: x -> fp16; weights -> fp16 transposed, q|k|v concatenated
    {
        int n4 = (BB * SS * DM) / 4;
        cvt_h_kernel<<<(n4 + 255) / 256, 256>>>((const float4*)x, (uint2*)xh, n4);
    }
    transpose_h_kernel<<<dim3((NH * HD) / 32, DM / 32), dim3(32, 8)>>>(
        wq, wqkvT, DM, NH * HD);
    transpose_h_kernel<<<dim3((NKV * HD) / 32, DM / 32), dim3(32, 8)>>>(
        wk, wqkvT + (size_t)(NH * HD) * DM, DM, NKV * HD);
    transpose_h_kernel<<<dim3((NKV * HD) / 32, DM / 32), dim3(32, 8)>>>(
        wv, wqkvT + (size_t)(NH * HD + NKV * HD) * DM, DM, NKV * HD);
    transpose_h_kernel<<<dim3(DM / 32, DM / 32), dim3(32, 8)>>>(wo, woT, DM, DM);

    // Fused QKV projection (one full-chip GEMM; per-block segment epilogue)
    gemm_f16_kernel<<<dim3(NQKV / 128, M / 128), 256, GEMM_SMEM>>>(
        xh, wqkvT, nullptr, M, NQKV, DM, /*mode=*/-1, q, k, v, fcos, fsin);

    // Pack V into key-pair-major b32
    {
        int tot = BB * NKV * (SS / 2) * HD;
        packv_kernel<<<tot / 256, 256>>>(v, vp);
    }

    // Attention
    attn_kernel<<<dim3(SS / 128, NH, BB), 256>>>(q, k, vp, att);

    // Output projection (fp32 epilogue to d_out)
    gemm_f16_kernel<<<dim3(DM / 128, M / 128), 256, GEMM_SMEM>>>(
        att, woT, out, M, DM, DM, /*mode=*/0, nullptr, nullptr, nullptr, fcos, fsin);
}

// round 9
// speedup vs baseline: 2.0642x; 1.0322x over previous
#include <cuda_runtime.h>
#include <cuda_fp16.h>
#include <cstdint>

// Problem constants
#define BB 2
#define SS 2048
#define DM 2048
#define NH 32
#define NKV 8
#define HD 64

#define LOG2E 1.4426950408889634f
#define NQKV (NH * HD + 2 * NKV * HD)   // 3072 concatenated output cols

// ---------------------------------------------------------------------------
// Scratch (allocation-free rule: __device__ globals)
// ---------------------------------------------------------------------------
__device__ __align__(1024) __half g_xh[(size_t)BB * SS * DM];
__device__ __align__(1024) __half g_wqkvT[(size_t)NQKV * DM];  // [3072, 2048]
__device__ __align__(1024) __half g_woT[(size_t)DM * DM];
__device__ __align__(1024) __half g_q[(size_t)BB * SS * NH * HD];
__device__ __align__(1024) __half g_k[(size_t)BB * SS * NKV * HD];
__device__ __align__(1024) __half g_att[(size_t)BB * SS * NH * HD];
__device__ __align__(1024) uint32_t g_vp[(size_t)BB * NKV * (SS / 2) * HD];

// ---------------------------------------------------------------------------
// Helpers
// ---------------------------------------------------------------------------
__device__ __forceinline__ uint32_t smem_u32(const void* p) {
    uint32_t a;
    asm("{ .reg .u64 t; cvta.to.shared.u64 t, %1; cvt.u32.u64 %0, t; }" : "=r"(a) : "l"(p));
    return a;
}
// pack two fp32 -> f16x2 (lo, hi) with round-to-nearest-even
__device__ __forceinline__ uint32_t h2pack(float lo, float hi) {
    uint32_t d;
    asm("cvt.rn.f16x2.f32 %0, %1, %2;" : "=r"(d) : "f"(hi), "f"(lo));
    return d;
}
__device__ __forceinline__ void cp_async16(uint32_t smem, const void* gmem) {
    asm volatile("cp.async.cg.shared.global [%0], [%1], 16;" :: "r"(smem), "l"(gmem));
}
#define CP_COMMIT() asm volatile("cp.async.commit_group;" ::: "memory")
#define CP_WAIT(n)  asm volatile("cp.async.wait_group %0;" :: "n"(n) : "memory")

// ldmatrix x4: four 8x8 b16 matrices
__device__ __forceinline__ void ldsm_x4(uint32_t& r0, uint32_t& r1,
                                        uint32_t& r2, uint32_t& r3, uint32_t addr) {
    asm volatile("ldmatrix.sync.aligned.m8n8.x4.shared.b16 {%0,%1,%2,%3}, [%4];"
                 : "=r"(r0), "=r"(r1), "=r"(r2), "=r"(r3) : "r"(addr));
}

// m16n8k16 fp16 MMA, fp32 accumulate (sm_80+ baseline; legacy HMMA pipe)
__device__ __forceinline__ void mma16n8k16(float* d, const uint32_t* a, const uint32_t* b) {
    asm volatile(
        "mma.sync.aligned.m16n8k16.row.col.f32.f16.f16.f32 "
        "{%0,%1,%2,%3}, {%4,%5,%6,%7}, {%8,%9}, {%0,%1,%2,%3};"
        : "+f"(d[0]), "+f"(d[1]), "+f"(d[2]), "+f"(d[3])
        : "r"(a[0]), "r"(a[1]), "r"(a[2]), "r"(a[3]), "r"(b[0]), "r"(b[1]));
}

// ---------------------------------------------------------------------------
// fp16 mma.sync GEMM: C = A[M,K] @ Bt[N,K]^T (fp16, K-major), ldmatrix frags.
// BM=BN=128, BK=32, 256 threads / 8 warps (warp tile 32x64), 4-stage cp.async,
// ONE barrier per k-iter (load target (s+3)%4 != read stage s%4), 2 blocks/SM.
// Epilogue modes: 0 = fp32 store to Cv; -1 = fused QKV (q: rope+scale, k: rope,
// v: fp16 packed key-pair-major direct to vp).
// ---------------------------------------------------------------------------
#define GLD 40                 // halves per smem row
#define GAH (128 * GLD)        // halves per operand tile (5120)
#define GSTH (2 * GAH)         // halves per stage (10240)
#define GEMM_SMEM (4 * GSTH * 2)

__global__ __launch_bounds__(256, 2) void gemm_f16_kernel(
    const __half* __restrict__ A, const __half* __restrict__ Bt,
    void* __restrict__ Cv, int M, int N, int K, int mode,
    __half* __restrict__ qd, __half* __restrict__ kd, uint32_t* __restrict__ vp,
    const float* __restrict__ fcos, const float* __restrict__ fsin)
{
    extern __shared__ __half smh[];
    const int tid = threadIdx.x;
    const int wid = tid >> 5, lid = tid & 31;
    const int wm = wid & 3, wn = wid >> 2;       // 4x2 warp grid
    const int lr = lid >> 2, lc = lid & 3;
    const int bm = blockIdx.y * 128, bn = blockIdx.x * 128;

    const uint32_t sb = smem_u32(smh);

    // ldmatrix lane base offsets (in halves)
    const uint32_t aLane = (uint32_t)((wm * 32 + (lid & 15)) * GLD + (lid >> 4) * 8);
    const uint32_t bLane = (uint32_t)((wn * 64 + (lid & 7) + ((lid >> 4) & 1) * 8) * GLD
                                      + ((lid >> 3) & 1) * 8);

    float acc[2][8][4];
#pragma unroll
    for (int mt = 0; mt < 2; mt++)
#pragma unroll
        for (int nt = 0; nt < 8; nt++)
#pragma unroll
            for (int i = 0; i < 4; i++) acc[mt][nt][i] = 0.f;

    auto load_stage = [&](int s) {
        const int st = s & 3;
        const __half* Ab = A + (size_t)bm * K + s * 32;
        const __half* Bb = Bt + (size_t)bn * K + s * 32;
#pragma unroll
        for (int i = 0; i < 2; i++) {
            int c = tid + i * 256;
            int row = c >> 2, cc = c & 3;        // 4 x 16B chunks per 32-half row
            cp_async16(sb + (uint32_t)(st * GSTH + row * GLD + cc * 8) * 2,
                       Ab + (size_t)row * K + cc * 8);
            cp_async16(sb + (uint32_t)(st * GSTH + GAH + row * GLD + cc * 8) * 2,
                       Bb + (size_t)row * K + cc * 8);
        }
    };

    const int nk = K / 32;
#pragma unroll
    for (int s = 0; s < 3; s++) { if (s < nk) load_stage(s); CP_COMMIT(); }

    for (int s = 0; s < nk; s++) {
        CP_WAIT(2);
        __syncthreads();                 // stage s%4 ready for everyone
        if (s + 3 < nk) load_stage(s + 3);   // writes (s+3)%4 != s%4 -> safe
        CP_COMMIT();                     // uniform group count
        const int st = s & 3;
        const uint32_t sa = sb + (uint32_t)(st * GSTH) * 2;
        const uint32_t sbB = sb + (uint32_t)(st * GSTH + GAH) * 2;
#pragma unroll
        for (int kk = 0; kk < 2; kk++) {         // two k16 steps cover BK=32
            uint32_t af[2][4], bf[8][2];
#pragma unroll
            for (int mt = 0; mt < 2; mt++)
                ldsm_x4(af[mt][0], af[mt][1], af[mt][2], af[mt][3],
                        sa + (aLane + (uint32_t)(mt * 16 * GLD + kk * 16)) * 2);
#pragma unroll
            for (int p = 0; p < 4; p++)
                ldsm_x4(bf[2 * p][0], bf[2 * p][1], bf[2 * p + 1][0], bf[2 * p + 1][1],
                        sbB + (bLane + (uint32_t)(p * 16 * GLD + kk * 16)) * 2);
#pragma unroll
            for (int mt = 0; mt < 2; mt++)
#pragma unroll
                for (int nt = 0; nt < 8; nt++)
                    mma16n8k16(acc[mt][nt], af[mt], bf[nt]);
        }
    }

    // epilogue: resolve destination segment (uniform per block)
    int emode = mode;
    int colb = bn;
    float scale = 1.0f;
    if (mode < 0) {
        if (bn < NH * HD)                 { emode = 1; colb = bn; scale = 0.125f * LOG2E; }
        else if (bn < NH * HD + NKV * HD) { emode = 2; colb = bn - NH * HD; }
        else                              { emode = 3; colb = bn - NH * HD - NKV * HD; }
    }

#pragma unroll
    for (int mt = 0; mt < 2; mt++) {
        const int r0 = bm + wm * 32 + mt * 16 + lr;
        const int s0 = r0 & (SS - 1);
        const int s1 = (r0 + 8) & (SS - 1);
#pragma unroll
        for (int nt = 0; nt < 8; nt++) {
            const int col = colb + wn * 64 + nt * 8 + lc * 2;
            float a0 = acc[mt][nt][0], a1 = acc[mt][nt][1];
            float a2 = acc[mt][nt][2], a3 = acc[mt][nt][3];
            if (emode == 0) {
                float* C = (float*)Cv;
                *(float2*)&C[(size_t)r0 * DM + col] = make_float2(a0, a1);
                *(float2*)&C[(size_t)(r0 + 8) * DM + col] = make_float2(a2, a3);
            } else if (emode == 3) {
                // fused key-pair pack: partner lane (lid^4) holds rows r0+1 / r0+9
                uint32_t w0 = h2pack(a0, a1);            // row r0,   cols col,col+1
                uint32_t w1 = h2pack(a2, a3);            // row r0+8
                uint32_t pw0 = __shfl_xor_sync(0xffffffffu, w0, 4);
                uint32_t pw1 = __shfl_xor_sync(0xffffffffu, w1, 4);
                if (!(lr & 1)) {   // even rows own the pair (r0, r0+1)
                    uint32_t lo0 = __byte_perm(w0, pw0, 0x5410);  // {V[r0][c],V[r0+1][c]}
                    uint32_t hi0 = __byte_perm(w0, pw0, 0x7632);  // col+1
                    uint32_t lo1 = __byte_perm(w1, pw1, 0x5410);
                    uint32_t hi1 = __byte_perm(w1, pw1, 0x7632);
                    const int bb = r0 >> 11;
                    const int sp = (r0 & (SS - 1)) >> 1;
                    const int kvh = col >> 6, d = col & 63;
                    uint32_t* dst = vp + ((size_t)(bb * NKV + kvh) * (SS / 2) + sp) * 64 + d;
                    *(uint2*)dst = make_uint2(lo0, hi0);
                    *(uint2*)(dst + 4 * 64) = make_uint2(lo1, hi1);   // rows r0+8,r0+9
                }
            } else {  // rope (a0/a1 and a2/a3 are the even/odd rotation pairs)
                const int Nd = (emode == 1) ? NH * HD : NKV * HD;
                __half* C = (emode == 1) ? qd : kd;
                const int pidx = (col & 63) >> 1;
                const float c0 = fcos[s0 * 32 + pidx], si0 = fsin[s0 * 32 + pidx];
                const float c1 = fcos[s1 * 32 + pidx], si1 = fsin[s1 * 32 + pidx];
                const float sc = (emode == 1) ? scale : 1.0f;
                *(uint32_t*)&C[(size_t)r0 * Nd + col] =
                    h2pack(sc * (a0 * c0 - a1 * si0), sc * (a0 * si0 + a1 * c0));
                *(uint32_t*)&C[(size_t)(r0 + 8) * Nd + col] =
                    h2pack(sc * (a2 * c1 - a3 * si1), sc * (a2 * si1 + a3 * c1));
            }
        }
    }
}

// ---------------------------------------------------------------------------
// Merged prepass: x -> fp16 (segment A) + 4 weight transposes (segments B-E).
// One launch replaces five.
// ---------------------------------------------------------------------------
__global__ __launch_bounds__(256) void prep_kernel(
    const float* __restrict__ x,
    const float* __restrict__ wq, const float* __restrict__ wk,
    const float* __restrict__ wv, const float* __restrict__ wo,
    __half* __restrict__ xh, __half* __restrict__ wqkvT, __half* __restrict__ woT)
{
    int bid = blockIdx.x;
    const int tid = threadIdx.x;

    if (bid < 8192) {   // segment A: convert x (2,097,152 float4s)
        int i = bid * 256 + tid;
        float4 v = ((const float4*)x)[i];
        uint2 o;
        o.x = h2pack(v.x, v.y);
        o.y = h2pack(v.z, v.w);
        ((uint2*)xh)[i] = o;
        return;
    }
    bid -= 8192;

    const float* src;
    __half* dst;
    int C;
    if (bid < 4096)      { src = wq; dst = wqkvT;                          C = NH * HD; }
    else if (bid < 5120) { bid -= 4096; src = wk; dst = wqkvT + (size_t)(NH * HD) * DM;            C = NKV * HD; }
    else if (bid < 6144) { bid -= 5120; src = wv; dst = wqkvT + (size_t)(NH * HD + NKV * HD) * DM; C = NKV * HD; }
    else                 { bid -= 6144; src = wo; dst = woT;               C = DM; }

    __shared__ float t[32][33];
    const int nbx = C / 32;
    const int bx = (bid % nbx) * 32;
    const int by = (bid / nbx) * 32;
    const int tx = tid & 31, ty = tid >> 5;
    const int xcol = bx + tx;
#pragma unroll
    for (int i = ty; i < 32; i += 8)
        t[i][tx] = src[(size_t)(by + i) * C + xcol];
    __syncthreads();
    const int xo = by + tx;
#pragma unroll
    for (int i = ty; i < 32; i += 8)
        dst[(size_t)(bx + i) * DM + xo] = __float2half(t[tx][i]);
}

// ---------------------------------------------------------------------------
// Flash attention (causal, GQA) via mma.sync fp16 (f32 accumulate).
// Block = 128 q-rows x head x batch; 8 warps, warp owns 16 rows.
// K frags via ldmatrix.x4; PV A-frags = f16x2 packs of the S accumulator (no
// shuffles); V pre-packed key-pair-major -> single-LDS32 B-frags.
// 2-stage cp.async double buffer, ONE barrier per iteration.
// exp2 domain (log2e folded into q scale).
// ---------------------------------------------------------------------------
#define AKLD 72      // halves per K row (64 + pad) -> 36-word stride
#define AVLD 72      // words per Vp row (64 + pad)
#define KS_H (64 * AKLD)
#define VP_W (32 * AVLD)

__global__ __launch_bounds__(256, 2) void attn_kernel(
    const __half* __restrict__ Q, const __half* __restrict__ Kg,
    const uint32_t* __restrict__ Vp, __half* __restrict__ O)
{
    __shared__ __align__(16) __half Ksm[2][KS_H];
    __shared__ __align__(16) uint32_t Vsm[2][VP_W];

    const int tile = gridDim.x - 1 - blockIdx.x;   // heavy tiles first
    const int m0 = tile * 128;
    const int h = blockIdx.y;
    const int b = blockIdx.z;
    const int kvh = h >> 2;
    const int tid = threadIdx.x;
    const int w = tid >> 5, lid = tid & 31;
    const int lr = lid >> 2, lc = lid & 3;
    const int row0 = m0 + w * 16 + lr;

    const int kvs = NKV * HD;  // 512
    const __half* Kbase = Kg + (size_t)b * SS * kvs + kvh * 64;
    const uint32_t* Vpb = Vp + ((size_t)(b * NKV + kvh) * (SS / 2)) * 64;

    const uint32_t kLane = (uint32_t)(((lid & 7) + ((lid >> 4) & 1) * 8) * AKLD
                                      + ((lid >> 3) & 1) * 8);

    // Persistent Q fragments (q has 0.125*log2e folded in, fp16)
    uint32_t qa[4][4];
    {
        const __half* q0 = Q + ((size_t)(b * SS + row0) * NH + h) * HD;
        const __half* q1 = q0 + (size_t)8 * NH * HD;
#pragma unroll
        for (int kk = 0; kk < 4; kk++) {
            qa[kk][0] = *(const uint32_t*)(q0 + kk * 16 + 2 * lc);
            qa[kk][1] = *(const uint32_t*)(q1 + kk * 16 + 2 * lc);
            qa[kk][2] = *(const uint32_t*)(q0 + kk * 16 + 2 * lc + 8);
            qa[kk][3] = *(const uint32_t*)(q1 + kk * 16 + 2 * lc + 8);
        }
    }

    float oacc[8][4];
#pragma unroll
    for (int nt = 0; nt < 8; nt++)
#pragma unroll
        for (int i = 0; i < 4; i++) oacc[nt][i] = 0.f;
    float mst0 = -1e30f, mst1 = -1e30f, lst0 = 0.f, lst1 = 0.f;

    const uint32_t ks_b = smem_u32(Ksm);
    const uint32_t vs_b = smem_u32(Vsm);

    auto loadKV = [&](int n0, int st) {
#pragma unroll
        for (int i = 0; i < 2; i++) {
            int c = tid + i * 256;
            int kr = c >> 3, kc = c & 7;
            cp_async16(ks_b + (uint32_t)(st * KS_H + kr * AKLD + kc * 8) * 2,
                       Kbase + (size_t)(n0 + kr) * kvs + kc * 8);
            int vr = c >> 4, vc = c & 15;
            cp_async16(vs_b + (uint32_t)(st * VP_W + vr * AVLD + vc * 4) * 4,
                       Vpb + (size_t)(n0 / 2 + vr) * 64 + vc * 4);
        }
    };

    const int niter = m0 / 64 + 2;
    loadKV(0, 0);
    CP_COMMIT();

    for (int it = 0; it < niter; it++) {
        const int n0 = it * 64;
        const int st = it & 1;
        CP_WAIT(0);
        __syncthreads();                       // stage st ready; prev reads done
        if (it + 1 < niter) loadKV(n0 + 64, st ^ 1);
        CP_COMMIT();

        const uint32_t ksa = ks_b + (uint32_t)(st * KS_H) * 2;
        const uint32_t* Vs = Vsm[st];

        float s[8][4];
#pragma unroll
        for (int nt = 0; nt < 8; nt++)
#pragma unroll
            for (int i = 0; i < 4; i++) s[nt][i] = 0.f;
#pragma unroll
        for (int kk = 0; kk < 4; kk++) {
            uint32_t kb[8][2];
#pragma unroll
            for (int p = 0; p < 4; p++)
                ldsm_x4(kb[2 * p][0], kb[2 * p][1], kb[2 * p + 1][0], kb[2 * p + 1][1],
                        ksa + (kLane + (uint32_t)(p * 16 * AKLD + kk * 16)) * 2);
#pragma unroll
            for (int nt = 0; nt < 8; nt++)
                mma16n8k16(s[nt], qa[kk], kb[nt]);
        }

        if (n0 + 63 > m0 + w * 16) {
#pragma unroll
            for (int nt = 0; nt < 8; nt++) {
                const int key0 = n0 + nt * 8 + 2 * lc;
                const int key1 = key0 + 1;
                if (key0 > row0) s[nt][0] = -1e30f;
                if (key1 > row0) s[nt][1] = -1e30f;
                if (key0 > row0 + 8) s[nt][2] = -1e30f;
                if (key1 > row0 + 8) s[nt][3] = -1e30f;
            }
        }

        float mx0 = -1e30f, mx1 = -1e30f;
#pragma unroll
        for (int nt = 0; nt < 8; nt++) {
            mx0 = fmaxf(mx0, fmaxf(s[nt][0], s[nt][1]));
            mx1 = fmaxf(mx1, fmaxf(s[nt][2], s[nt][3]));
        }
        mx0 = fmaxf(mx0, __shfl_xor_sync(0xffffffffu, mx0, 1));
        mx0 = fmaxf(mx0, __shfl_xor_sync(0xffffffffu, mx0, 2));
        mx1 = fmaxf(mx1, __shfl_xor_sync(0xffffffffu, mx1, 1));
        mx1 = fmaxf(mx1, __shfl_xor_sync(0xffffffffu, mx1, 2));
        const float mn0 = fmaxf(mst0, mx0), mn1 = fmaxf(mst1, mx1);
        const float corr0 = exp2f(mst0 - mn0), corr1 = exp2f(mst1 - mn1);
        mst0 = mn0; mst1 = mn1;
        float sum0 = 0.f, sum1 = 0.f;
#pragma unroll
        for (int nt = 0; nt < 8; nt++) {
            s[nt][0] = exp2f(s[nt][0] - mn0); sum0 += s[nt][0];
            s[nt][1] = exp2f(s[nt][1] - mn0); sum0 += s[nt][1];
            s[nt][2] = exp2f(s[nt][2] - mn1); sum1 += s[nt][2];
            s[nt][3] = exp2f(s[nt][3] - mn1); sum1 += s[nt][3];
        }
        sum0 += __shfl_xor_sync(0xffffffffu, sum0, 1);
        sum0 += __shfl_xor_sync(0xffffffffu, sum0, 2);
        sum1 += __shfl_xor_sync(0xffffffffu, sum1, 1);
        sum1 += __shfl_xor_sync(0xffffffffu, sum1, 2);
        lst0 = lst0 * corr0 + sum0;
        lst1 = lst1 * corr1 + sum1;
#pragma unroll
        for (int nt = 0; nt < 8; nt++) {
            oacc[nt][0] *= corr0; oacc[nt][1] *= corr0;
            oacc[nt][2] *= corr1; oacc[nt][3] *= corr1;
        }

#pragma unroll
        for (int kk = 0; kk < 4; kk++) {
            uint32_t pa[4];
            pa[0] = h2pack(s[2 * kk][0], s[2 * kk][1]);
            pa[1] = h2pack(s[2 * kk][2], s[2 * kk][3]);
            pa[2] = h2pack(s[2 * kk + 1][0], s[2 * kk + 1][1]);
            pa[3] = h2pack(s[2 * kk + 1][2], s[2 * kk + 1][3]);
#pragma unroll
            for (int nt = 0; nt < 8; nt++) {
                uint32_t vb[2];
                const uint32_t* p = &Vs[(kk * 8 + lc) * AVLD + nt * 8 + lr];
                vb[0] = p[0];
                vb[1] = p[4 * AVLD];
                mma16n8k16(oacc[nt], pa, vb);
            }
        }
    }

    const float inv0 = 1.f / lst0, inv1 = 1.f / lst1;
    __half* o0 = O + ((size_t)(b * SS + row0) * NH + h) * HD;
    __half* o1 = o0 + (size_t)8 * NH * HD;
#pragma unroll
    for (int nt = 0; nt < 8; nt++) {
        const int col = nt * 8 + lc * 2;
        *(uint32_t*)&o0[col] = h2pack(oacc[nt][0] * inv0, oacc[nt][1] * inv0);
        *(uint32_t*)&o1[col] = h2pack(oacc[nt][2] * inv1, oacc[nt][3] * inv1);
    }
}

// ---------------------------------------------------------------------------
// Launch. inputs: 0=x, 1=freqs_cos, 2=freqs_sin, 3=mask(unused),
//                 4=wq, 5=wk, 6=wv, 7=wo
// ---------------------------------------------------------------------------
extern "C" void kernel_launch(void* const* d_in, const int* in_sizes, int n_in,
                              void* d_out, int out_size)
{
    const float* x = (const float*)d_in[0];
    const float* fcos = (const float*)d_in[1];
    const float* fsin = (const float*)d_in[2];
    const float* wq = (const float*)d_in[4];
    const float* wk = (const float*)d_in[5];
    const float* wv = (const float*)d_in[6];
    const float* wo = (const float*)d_in[7];
    float* out = (float*)d_out;

    __half *xh, *wqkvT, *woT, *q, *k, *att;
    uint32_t* vp;
    cudaGetSymbolAddress((void**)&xh, g_xh);
    cudaGetSymbolAddress((void**)&wqkvT, g_wqkvT);
    cudaGetSymbolAddress((void**)&woT, g_woT);
    cudaGetSymbolAddress((void**)&q, g_q);
    cudaGetSymbolAddress((void**)&k, g_k);
    cudaGetSymbolAddress((void**)&att, g_att);
    cudaGetSymbolAddress((void**)&vp, g_vp);

    static bool attr_set = false;
    if (!attr_set) {
        cudaFuncSetAttribute(gemm_f16_kernel,
                             cudaFuncAttributeMaxDynamicSharedMemorySize, GEMM_SMEM);
        attr_set = true;
    }

    const int M = BB * SS;  // 4096

    // Merged prepass: x -> fp16 + all weight transposes in one launch
    prep_kernel<<<8192 + 4096 + 1024 + 1024 + 4096, 256>>>(
        x, wq, wk, wv, wo, xh, wqkvT, woT);

    // Fused QKV projection; v segment writes key-pair-packed vp directly
    gemm_f16_kernel<<<dim3(NQKV / 128, M / 128), 256, GEMM_SMEM>>>(
        xh, wqkvT, nullptr, M, NQKV, DM, /*mode=*/-1, q, k, vp, fcos, fsin);

    // Attention
    attn_kernel<<<dim3(SS / 128, NH, BB), 256>>>(q, k, vp, att);

    // Output projection (fp32 epilogue to d_out)
    gemm_f16_kernel<<<dim3(DM / 128, M / 128), 256, GEMM_SMEM>>>(
        att, woT, out, M, DM, DM, /*mode=*/0, nullptr, nullptr, nullptr, fcos, fsin);
}

// round 10
// speedup vs baseline: 2.1981x; 1.0649x over previous
#include <cuda_runtime.h>
#include <cuda_fp16.h>
#include <cstdint>

// Problem constants
#define BB 2
#define SS 2048
#define DM 2048
#define NH 32
#define NKV 8
#define HD 64

#define LOG2E 1.4426950408889634f
#define NQKV (NH * HD + 2 * NKV * HD)   // 3072 concatenated output cols

// ---------------------------------------------------------------------------
// Scratch (allocation-free rule: __device__ globals)
// ---------------------------------------------------------------------------
__device__ __align__(1024) __half g_xh[(size_t)BB * SS * DM];
__device__ __align__(1024) __half g_wqkvT[(size_t)NQKV * DM];  // [3072, 2048]
__device__ __align__(1024) __half g_woT[(size_t)DM * DM];
__device__ __align__(1024) __half g_q[(size_t)BB * SS * NH * HD];
__device__ __align__(1024) __half g_k[(size_t)BB * SS * NKV * HD];
__device__ __align__(1024) __half g_att[(size_t)BB * SS * NH * HD];
__device__ __align__(1024) uint32_t g_vp[(size_t)BB * NKV * (SS / 2) * HD];

// ---------------------------------------------------------------------------
// Helpers
// ---------------------------------------------------------------------------
__device__ __forceinline__ uint32_t smem_u32(const void* p) {
    uint32_t a;
    asm("{ .reg .u64 t; cvta.to.shared.u64 t, %1; cvt.u32.u64 %0, t; }" : "=r"(a) : "l"(p));
    return a;
}
// pack two fp32 -> f16x2 (lo, hi) with round-to-nearest-even
__device__ __forceinline__ uint32_t h2pack(float lo, float hi) {
    uint32_t d;
    asm("cvt.rn.f16x2.f32 %0, %1, %2;" : "=r"(d) : "f"(hi), "f"(lo));
    return d;
}
__device__ __forceinline__ void cp_async16(uint32_t smem, const void* gmem) {
    asm volatile("cp.async.cg.shared.global [%0], [%1], 16;" :: "r"(smem), "l"(gmem));
}
#define CP_COMMIT() asm volatile("cp.async.commit_group;" ::: "memory")
#define CP_WAIT(n)  asm volatile("cp.async.wait_group %0;" :: "n"(n) : "memory")

// ldmatrix x4: four 8x8 b16 matrices
__device__ __forceinline__ void ldsm_x4(uint32_t& r0, uint32_t& r1,
                                        uint32_t& r2, uint32_t& r3, uint32_t addr) {
    asm volatile("ldmatrix.sync.aligned.m8n8.x4.shared.b16 {%0,%1,%2,%3}, [%4];"
                 : "=r"(r0), "=r"(r1), "=r"(r2), "=r"(r3) : "r"(addr));
}

// m16n8k16 fp16 MMA, fp32 accumulate (sm_80+ baseline; legacy HMMA pipe)
__device__ __forceinline__ void mma16n8k16(float* d, const uint32_t* a, const uint32_t* b) {
    asm volatile(
        "mma.sync.aligned.m16n8k16.row.col.f32.f16.f16.f32 "
        "{%0,%1,%2,%3}, {%4,%5,%6,%7}, {%8,%9}, {%0,%1,%2,%3};"
        : "+f"(d[0]), "+f"(d[1]), "+f"(d[2]), "+f"(d[3])
        : "r"(a[0]), "r"(a[1]), "r"(a[2]), "r"(a[3]), "r"(b[0]), "r"(b[1]));
}

// ---------------------------------------------------------------------------
// fp16 mma.sync GEMM: C = A[M,K] @ Bt[N,K]^T (fp16, K-major), ldmatrix frags.
// BM=BN=128, BK=64, 256 threads / 8 warps (warp tile 32x64), 3-stage cp.async,
// ONE barrier per 64-deep k-iter (64 MMAs/warp between syncs), 2 blocks/SM.
// Epilogue modes: 0 = fp32 store to Cv; -1 = fused QKV (q: rope+scale, k: rope,
// v: fp16 packed key-pair-major direct to vp).
// ---------------------------------------------------------------------------
#define GLD 72                 // halves per smem row (64 + 8 pad)
#define GAH (128 * GLD)        // halves per operand tile (9216)
#define GSTH (2 * GAH)         // halves per stage (18432)
#define GEMM_SMEM (3 * GSTH * 2)   // 110592 B

__global__ __launch_bounds__(256, 2) void gemm_f16_kernel(
    const __half* __restrict__ A, const __half* __restrict__ Bt,
    void* __restrict__ Cv, int M, int N, int K, int mode,
    __half* __restrict__ qd, __half* __restrict__ kd, uint32_t* __restrict__ vp,
    const float* __restrict__ fcos, const float* __restrict__ fsin)
{
    extern __shared__ __half smh[];
    const int tid = threadIdx.x;
    const int wid = tid >> 5, lid = tid & 31;
    const int wm = wid & 3, wn = wid >> 2;       // 4x2 warp grid
    const int lr = lid >> 2, lc = lid & 3;
    const int bm = blockIdx.y * 128, bn = blockIdx.x * 128;

    const uint32_t sb = smem_u32(smh);

    // ldmatrix lane base offsets (in halves)
    const uint32_t aLane = (uint32_t)((wm * 32 + (lid & 15)) * GLD + (lid >> 4) * 8);
    const uint32_t bLane = (uint32_t)((wn * 64 + (lid & 7) + ((lid >> 4) & 1) * 8) * GLD
                                      + ((lid >> 3) & 1) * 8);

    float acc[2][8][4];
#pragma unroll
    for (int mt = 0; mt < 2; mt++)
#pragma unroll
        for (int nt = 0; nt < 8; nt++)
#pragma unroll
            for (int i = 0; i < 4; i++) acc[mt][nt][i] = 0.f;

    // one stage = 128 rows x 64 halves per operand; 8 x 16B chunks per row
    auto load_stage = [&](int s) {
        const int st = s % 3;
        const __half* Ab = A + (size_t)bm * K + s * 64;
        const __half* Bb = Bt + (size_t)bn * K + s * 64;
#pragma unroll
        for (int i = 0; i < 4; i++) {
            int c = tid + i * 256;
            int row = c >> 3, cc = c & 7;
            cp_async16(sb + (uint32_t)(st * GSTH + row * GLD + cc * 8) * 2,
                       Ab + (size_t)row * K + cc * 8);
            cp_async16(sb + (uint32_t)(st * GSTH + GAH + row * GLD + cc * 8) * 2,
                       Bb + (size_t)row * K + cc * 8);
        }
    };

    const int nk = K / 64;
    load_stage(0); CP_COMMIT();
    load_stage(1); CP_COMMIT();

    for (int s = 0; s < nk; s++) {
        CP_WAIT(1);
        __syncthreads();                    // stage s%3 ready; stage (s+2)%3 free
        if (s + 2 < nk) load_stage(s + 2);
        CP_COMMIT();                        // uniform group count
        const int st = s % 3;
        const uint32_t sa = sb + (uint32_t)(st * GSTH) * 2;
        const uint32_t sbB = sb + (uint32_t)(st * GSTH + GAH) * 2;
#pragma unroll
        for (int kk = 0; kk < 4; kk++) {    // four k16 steps cover BK=64
            uint32_t af[2][4], bf[8][2];
#pragma unroll
            for (int mt = 0; mt < 2; mt++)
                ldsm_x4(af[mt][0], af[mt][1], af[mt][2], af[mt][3],
                        sa + (aLane + (uint32_t)(mt * 16 * GLD + kk * 16)) * 2);
#pragma unroll
            for (int p = 0; p < 4; p++)
                ldsm_x4(bf[2 * p][0], bf[2 * p][1], bf[2 * p + 1][0], bf[2 * p + 1][1],
                        sbB + (bLane + (uint32_t)(p * 16 * GLD + kk * 16)) * 2);
#pragma unroll
            for (int mt = 0; mt < 2; mt++)
#pragma unroll
                for (int nt = 0; nt < 8; nt++)
                    mma16n8k16(acc[mt][nt], af[mt], bf[nt]);
        }
    }

    // epilogue: resolve destination segment (uniform per block)
    int emode = mode;
    int colb = bn;
    float scale = 1.0f;
    if (mode < 0) {
        if (bn < NH * HD)                 { emode = 1; colb = bn; scale = 0.125f * LOG2E; }
        else if (bn < NH * HD + NKV * HD) { emode = 2; colb = bn - NH * HD; }
        else                              { emode = 3; colb = bn - NH * HD - NKV * HD; }
    }

#pragma unroll
    for (int mt = 0; mt < 2; mt++) {
        const int r0 = bm + wm * 32 + mt * 16 + lr;
        const int s0 = r0 & (SS - 1);
        const int s1 = (r0 + 8) & (SS - 1);
#pragma unroll
        for (int nt = 0; nt < 8; nt++) {
            const int col = colb + wn * 64 + nt * 8 + lc * 2;
            float a0 = acc[mt][nt][0], a1 = acc[mt][nt][1];
            float a2 = acc[mt][nt][2], a3 = acc[mt][nt][3];
            if (emode == 0) {
                float* C = (float*)Cv;
                *(float2*)&C[(size_t)r0 * DM + col] = make_float2(a0, a1);
                *(float2*)&C[(size_t)(r0 + 8) * DM + col] = make_float2(a2, a3);
            } else if (emode == 3) {
                // fused key-pair pack: partner lane (lid^4) holds rows r0+1 / r0+9
                uint32_t w0 = h2pack(a0, a1);
                uint32_t w1 = h2pack(a2, a3);
                uint32_t pw0 = __shfl_xor_sync(0xffffffffu, w0, 4);
                uint32_t pw1 = __shfl_xor_sync(0xffffffffu, w1, 4);
                if (!(lr & 1)) {   // even rows own the pair (r0, r0+1)
                    uint32_t lo0 = __byte_perm(w0, pw0, 0x5410);
                    uint32_t hi0 = __byte_perm(w0, pw0, 0x7632);
                    uint32_t lo1 = __byte_perm(w1, pw1, 0x5410);
                    uint32_t hi1 = __byte_perm(w1, pw1, 0x7632);
                    const int bb = r0 >> 11;
                    const int sp = (r0 & (SS - 1)) >> 1;
                    const int kvh = col >> 6, d = col & 63;
                    uint32_t* dst = vp + ((size_t)(bb * NKV + kvh) * (SS / 2) + sp) * 64 + d;
                    *(uint2*)dst = make_uint2(lo0, hi0);
                    *(uint2*)(dst + 4 * 64) = make_uint2(lo1, hi1);
                }
            } else {  // rope (a0/a1 and a2/a3 are the even/odd rotation pairs)
                const int Nd = (emode == 1) ? NH * HD : NKV * HD;
                __half* C = (emode == 1) ? qd : kd;
                const int pidx = (col & 63) >> 1;
                const float c0 = fcos[s0 * 32 + pidx], si0 = fsin[s0 * 32 + pidx];
                const float c1 = fcos[s1 * 32 + pidx], si1 = fsin[s1 * 32 + pidx];
                const float sc = (emode == 1) ? scale : 1.0f;
                *(uint32_t*)&C[(size_t)r0 * Nd + col] =
                    h2pack(sc * (a0 * c0 - a1 * si0), sc * (a0 * si0 + a1 * c0));
                *(uint32_t*)&C[(size_t)(r0 + 8) * Nd + col] =
                    h2pack(sc * (a2 * c1 - a3 * si1), sc * (a2 * si1 + a3 * c1));
            }
        }
    }
}

// ---------------------------------------------------------------------------
// Merged prepass: x -> fp16 (segment A) + 4 weight transposes (segments B-E).
// ---------------------------------------------------------------------------
__global__ __launch_bounds__(256) void prep_kernel(
    const float* __restrict__ x,
    const float* __restrict__ wq, const float* __restrict__ wk,
    const float* __restrict__ wv, const float* __restrict__ wo,
    __half* __restrict__ xh, __half* __restrict__ wqkvT, __half* __restrict__ woT)
{
    int bid = blockIdx.x;
    const int tid = threadIdx.x;

    if (bid < 8192) {   // segment A: convert x (2,097,152 float4s)
        int i = bid * 256 + tid;
        float4 v = ((const float4*)x)[i];
        uint2 o;
        o.x = h2pack(v.x, v.y);
        o.y = h2pack(v.z, v.w);
        ((uint2*)xh)[i] = o;
        return;
    }
    bid -= 8192;

    const float* src;
    __half* dst;
    int C;
    if (bid < 4096)      { src = wq; dst = wqkvT;                          C = NH * HD; }
    else if (bid < 5120) { bid -= 4096; src = wk; dst = wqkvT + (size_t)(NH * HD) * DM;            C = NKV * HD; }
    else if (bid < 6144) { bid -= 5120; src = wv; dst = wqkvT + (size_t)(NH * HD + NKV * HD) * DM; C = NKV * HD; }
    else                 { bid -= 6144; src = wo; dst = woT;               C = DM; }

    __shared__ float t[32][33];
    const int nbx = C / 32;
    const int bx = (bid % nbx) * 32;
    const int by = (bid / nbx) * 32;
    const int tx = tid & 31, ty = tid >> 5;
    const int xcol = bx + tx;
#pragma unroll
    for (int i = ty; i < 32; i += 8)
        t[i][tx] = src[(size_t)(by + i) * C + xcol];
    __syncthreads();
    const int xo = by + tx;
#pragma unroll
    for (int i = ty; i < 32; i += 8)
        dst[(size_t)(bx + i) * DM + xo] = __float2half(t[tx][i]);
}

// ---------------------------------------------------------------------------
// Flash attention (causal, GQA) via mma.sync fp16 (f32 accumulate).
// Block = 128 q-rows x head x batch; 8 warps, warp owns 16 rows.
// K frags via ldmatrix.x4; PV A-frags = f16x2 packs of the S accumulator;
// V pre-packed key-pair-major -> single-LDS32 B-frags.
// 2-stage cp.async double buffer, ONE barrier per iteration. exp2 softmax.
// ---------------------------------------------------------------------------
#define AKLD 72      // halves per K row (64 + pad)
#define AVLD 72      // words per Vp row (64 + pad)
#define KS_H (64 * AKLD)
#define VP_W (32 * AVLD)

__global__ __launch_bounds__(256, 2) void attn_kernel(
    const __half* __restrict__ Q, const __half* __restrict__ Kg,
    const uint32_t* __restrict__ Vp, __half* __restrict__ O)
{
    __shared__ __align__(16) __half Ksm[2][KS_H];
    __shared__ __align__(16) uint32_t Vsm[2][VP_W];

    const int tile = gridDim.x - 1 - blockIdx.x;   // heavy tiles first
    const int m0 = tile * 128;
    const int h = blockIdx.y;
    const int b = blockIdx.z;
    const int kvh = h >> 2;
    const int tid = threadIdx.x;
    const int w = tid >> 5, lid = tid & 31;
    const int lr = lid >> 2, lc = lid & 3;
    const int row0 = m0 + w * 16 + lr;

    const int kvs = NKV * HD;  // 512
    const __half* Kbase = Kg + (size_t)b * SS * kvs + kvh * 64;
    const uint32_t* Vpb = Vp + ((size_t)(b * NKV + kvh) * (SS / 2)) * 64;

    const uint32_t kLane = (uint32_t)(((lid & 7) + ((lid >> 4) & 1) * 8) * AKLD
                                      + ((lid >> 3) & 1) * 8);

    // Persistent Q fragments (q has 0.125*log2e folded in, fp16)
    uint32_t qa[4][4];
    {
        const __half* q0 = Q + ((size_t)(b * SS + row0) * NH + h) * HD;
        const __half* q1 = q0 + (size_t)8 * NH * HD;
#pragma unroll
        for (int kk = 0; kk < 4; kk++) {
            qa[kk][0] = *(const uint32_t*)(q0 + kk * 16 + 2 * lc);
            qa[kk][1] = *(const uint32_t*)(q1 + kk * 16 + 2 * lc);
            qa[kk][2] = *(const uint32_t*)(q0 + kk * 16 + 2 * lc + 8);
            qa[kk][3] = *(const uint32_t*)(q1 + kk * 16 + 2 * lc + 8);
        }
    }

    float oacc[8][4];
#pragma unroll
    for (int nt = 0; nt < 8; nt++)
#pragma unroll
        for (int i = 0; i < 4; i++) oacc[nt][i] = 0.f;
    float mst0 = -1e30f, mst1 = -1e30f, lst0 = 0.f, lst1 = 0.f;

    const uint32_t ks_b = smem_u32(Ksm);
    const uint32_t vs_b = smem_u32(Vsm);

    auto loadKV = [&](int n0, int st) {
#pragma unroll
        for (int i = 0; i < 2; i++) {
            int c = tid + i * 256;
            int kr = c >> 3, kc = c & 7;
            cp_async16(ks_b + (uint32_t)(st * KS_H + kr * AKLD + kc * 8) * 2,
                       Kbase + (size_t)(n0 + kr) * kvs + kc * 8);
            int vr = c >> 4, vc = c & 15;
            cp_async16(vs_b + (uint32_t)(st * VP_W + vr * AVLD + vc * 4) * 4,
                       Vpb + (size_t)(n0 / 2 + vr) * 64 + vc * 4);
        }
    };

    const int niter = m0 / 64 + 2;
    loadKV(0, 0);
    CP_COMMIT();

    for (int it = 0; it < niter; it++) {
        const int n0 = it * 64;
        const int st = it & 1;
        CP_WAIT(0);
        __syncthreads();
        if (it + 1 < niter) loadKV(n0 + 64, st ^ 1);
        CP_COMMIT();

        const uint32_t ksa = ks_b + (uint32_t)(st * KS_H) * 2;
        const uint32_t* Vs = Vsm[st];

        float s[8][4];
#pragma unroll
        for (int nt = 0; nt < 8; nt++)
#pragma unroll
            for (int i = 0; i < 4; i++) s[nt][i] = 0.f;
#pragma unroll
        for (int kk = 0; kk < 4; kk++) {
            uint32_t kb[8][2];
#pragma unroll
            for (int p = 0; p < 4; p++)
                ldsm_x4(kb[2 * p][0], kb[2 * p][1], kb[2 * p + 1][0], kb[2 * p + 1][1],
                        ksa + (kLane + (uint32_t)(p * 16 * AKLD + kk * 16)) * 2);
#pragma unroll
            for (int nt = 0; nt < 8; nt++)
                mma16n8k16(s[nt], qa[kk], kb[nt]);
        }

        if (n0 + 63 > m0 + w * 16) {
#pragma unroll
            for (int nt = 0; nt < 8; nt++) {
                const int key0 = n0 + nt * 8 + 2 * lc;
                const int key1 = key0 + 1;
                if (key0 > row0) s[nt][0] = -1e30f;
                if (key1 > row0) s[nt][1] = -1e30f;
                if (key0 > row0 + 8) s[nt][2] = -1e30f;
                if (key1 > row0 + 8) s[nt][3] = -1e30f;
            }
        }

        float mx0 = -1e30f, mx1 = -1e30f;
#pragma unroll
        for (int nt = 0; nt < 8; nt++) {
            mx0 = fmaxf(mx0, fmaxf(s[nt][0], s[nt][1]));
            mx1 = fmaxf(mx1, fmaxf(s[nt][2], s[nt][3]));
        }
        mx0 = fmaxf(mx0, __shfl_xor_sync(0xffffffffu, mx0, 1));
        mx0 = fmaxf(mx0, __shfl_xor_sync(0xffffffffu, mx0, 2));
        mx1 = fmaxf(mx1, __shfl_xor_sync(0xffffffffu, mx1, 1));
        mx1 = fmaxf(mx1, __shfl_xor_sync(0xffffffffu, mx1, 2));
        const float mn0 = fmaxf(mst0, mx0), mn1 = fmaxf(mst1, mx1);
        const float corr0 = exp2f(mst0 - mn0), corr1 = exp2f(mst1 - mn1);
        mst0 = mn0; mst1 = mn1;
        float sum0 = 0.f, sum1 = 0.f;
#pragma unroll
        for (int nt = 0; nt < 8; nt++) {
            s[nt][0] = exp2f(s[nt][0] - mn0); sum0 += s[nt][0];
            s[nt][1] = exp2f(s[nt][1] - mn0); sum0 += s[nt][1];
            s[nt][2] = exp2f(s[nt][2] - mn1); sum1 += s[nt][2];
            s[nt][3] = exp2f(s[nt][3] - mn1); sum1 += s[nt][3];
        }
        sum0 += __shfl_xor_sync(0xffffffffu, sum0, 1);
        sum0 += __shfl_xor_sync(0xffffffffu, sum0, 2);
        sum1 += __shfl_xor_sync(0xffffffffu, sum1, 1);
        sum1 += __shfl_xor_sync(0xffffffffu, sum1, 2);
        lst0 = lst0 * corr0 + sum0;
        lst1 = lst1 * corr1 + sum1;
#pragma unroll
        for (int nt = 0; nt < 8; nt++) {
            oacc[nt][0] *= corr0; oacc[nt][1] *= corr0;
            oacc[nt][2] *= corr1; oacc[nt][3] *= corr1;
        }

#pragma unroll
        for (int kk = 0; kk < 4; kk++) {
            uint32_t pa[4];
            pa[0] = h2pack(s[2 * kk][0], s[2 * kk][1]);
            pa[1] = h2pack(s[2 * kk][2], s[2 * kk][3]);
            pa[2] = h2pack(s[2 * kk + 1][0], s[2 * kk + 1][1]);
            pa[3] = h2pack(s[2 * kk + 1][2], s[2 * kk + 1][3]);
#pragma unroll
            for (int nt = 0; nt < 8; nt++) {
                uint32_t vb[2];
                const uint32_t* p = &Vs[(kk * 8 + lc) * AVLD + nt * 8 + lr];
                vb[0] = p[0];
                vb[1] = p[4 * AVLD];
                mma16n8k16(oacc[nt], pa, vb);
            }
        }
    }

    const float inv0 = 1.f / lst0, inv1 = 1.f / lst1;
    __half* o0 = O + ((size_t)(b * SS + row0) * NH + h) * HD;
    __half* o1 = o0 + (size_t)8 * NH * HD;
#pragma unroll
    for (int nt = 0; nt < 8; nt++) {
        const int col = nt * 8 + lc * 2;
        *(uint32_t*)&o0[col] = h2pack(oacc[nt][0] * inv0, oacc[nt][1] * inv0);
        *(uint32_t*)&o1[col] = h2pack(oacc[nt][2] * inv1, oacc[nt][3] * inv1);
    }
}

// ---------------------------------------------------------------------------
// Launch. inputs: 0=x, 1=freqs_cos, 2=freqs_sin, 3=mask(unused),
//                 4=wq, 5=wk, 6=wv, 7=wo
// ---------------------------------------------------------------------------
extern "C" void kernel_launch(void* const* d_in, const int* in_sizes, int n_in,
                              void* d_out, int out_size)
{
    const float* x = (const float*)d_in[0];
    const float* fcos = (const float*)d_in[1];
    const float* fsin = (const float*)d_in[2];
    const float* wq = (const float*)d_in[4];
    const float* wk = (const float*)d_in[5];
    const float* wv = (const float*)d_in[6];
    const float* wo = (const float*)d_in[7];
    float* out = (float*)d_out;

    __half *xh, *wqkvT, *woT, *q, *k, *att;
    uint32_t* vp;
    cudaGetSymbolAddress((void**)&xh, g_xh);
    cudaGetSymbolAddress((void**)&wqkvT, g_wqkvT);
    cudaGetSymbolAddress((void**)&woT, g_woT);
    cudaGetSymbolAddress((void**)&q, g_q);
    cudaGetSymbolAddress((void**)&k, g_k);
    cudaGetSymbolAddress((void**)&att, g_att);
    cudaGetSymbolAddress((void**)&vp, g_vp);

    static bool attr_set = false;
    if (!attr_set) {
        cudaFuncSetAttribute(gemm_f16_kernel,
                             cudaFuncAttributeMaxDynamicSharedMemorySize, GEMM_SMEM);
        attr_set = true;
    }

    const int M = BB * SS;  // 4096

    // Merged prepass: x -> fp16 + all weight transposes in one launch
    prep_kernel<<<8192 + 4096 + 1024 + 1024 + 4096, 256>>>(
        x, wq, wk, wv, wo, xh, wqkvT, woT);

    // Fused QKV projection; v segment writes key-pair-packed vp directly
    gemm_f16_kernel<<<dim3(NQKV / 128, M / 128), 256, GEMM_SMEM>>>(
        xh, wqkvT, nullptr, M, NQKV, DM, /*mode=*/-1, q, k, vp, fcos, fsin);

    // Attention
    attn_kernel<<<dim3(SS / 128, NH, BB), 256>>>(q, k, vp, att);

    // Output projection (fp32 epilogue to d_out)
    gemm_f16_kernel<<<dim3(DM / 128, M / 128), 256, GEMM_SMEM>>>(
        att, woT, out, M, DM, DM, /*mode=*/0, nullptr, nullptr, nullptr, fcos, fsin);
}